// round 7
// baseline (speedup 1.0000x reference)
#include <cuda_runtime.h>
#include <cstdint>

// ---------------------------------------------------------------------------
// Problem constants (fixed by setup_inputs)
// ---------------------------------------------------------------------------
#define TDOCS 4096
#define TSEQ  64
#define DIM   128
#define HID   128
#define GATES 512      // 4*HID
#define TILE1 32       // docs per CTA (layer 1)
#define KC1   32       // k-chunk (layer 1)
#define NCH1  8        // 256 / 32
#define NT1   512      // threads per CTA (layer 1): 16 warps, 4 per SMSP

#define NNODES 512     // G*N = 8*64
#define KSTEPS 8
#define HID2   64
#define GATES2 256     // 4*HID2
#define KTOT2  320     // 256 (x) + 64 (h)
#define TILE2  8
#define KC2    64
#define NCH2   5       // 320 / 64

// ---------------------------------------------------------------------------
// Device scratch (static; no allocations anywhere)
// ---------------------------------------------------------------------------
__device__ float g_Wt1[2 * 256 * GATES];      // [dir][k][gate]   (1 MB)
__device__ float g_Wt2[2 * KTOT2 * GATES2];   // [dir][k][gate]   (640 KB)
__device__ float g_demb[TDOCS * 256];         // doc embeddings   (4 MB)
__device__ int   g_perm[TDOCS];               // docs sorted by length, desc

// ---------------------------------------------------------------------------
// Helpers
// ---------------------------------------------------------------------------
__device__ __forceinline__ float sigf(float x) {
    return __fdividef(1.f, 1.f + __expf(-x));
}
__device__ __forceinline__ float tanh_f(float x) {
    return fmaf(2.f, __fdividef(1.f, 1.f + __expf(-2.f * x)), -1.f);
}
__device__ __forceinline__ void cp_async16(void* dst_smem, const void* src_gmem) {
    unsigned s = (unsigned)__cvta_generic_to_shared(dst_smem);
    asm volatile("cp.async.ca.shared.global [%0], [%1], 16;\n" :: "r"(s), "l"(src_gmem));
}
__device__ __forceinline__ void cp_commit() { asm volatile("cp.async.commit_group;\n"); }
__device__ __forceinline__ void cp_wait1()  { asm volatile("cp.async.wait_group 1;\n"); }
__device__ __forceinline__ void cp_wait0()  { asm volatile("cp.async.wait_group 0;\n"); }

// Packed fp32x2 (issue-slot compression; pipe throughput same as 2x FFMA)
__device__ __forceinline__ void ffma2(unsigned long long& d,
                                      unsigned long long a, unsigned long long b) {
    asm("fma.rn.f32x2 %0, %1, %2, %0;" : "+l"(d) : "l"(a), "l"(b));
}
__device__ __forceinline__ unsigned long long dup2(float x) {
    unsigned long long r;
    asm("mov.b64 %0, {%1, %1};" : "=l"(r) : "f"(x));
    return r;
}
__device__ __forceinline__ float2 unpack2(unsigned long long v) {
    float2 r;
    asm("mov.b64 {%0, %1}, %2;" : "=f"(r.x), "=f"(r.y) : "l"(v));
    return r;
}

// ---------------------------------------------------------------------------
// Prep: transpose weights to k-major
// ---------------------------------------------------------------------------
__global__ void transpose1_kernel(const float* __restrict__ Wihf, const float* __restrict__ Whhf,
                                  const float* __restrict__ Wihb, const float* __restrict__ Whhb) {
    int g = blockIdx.x, k = threadIdx.x, dir = blockIdx.y;
    const float* Wih = dir ? Wihb : Wihf;
    const float* Whh = dir ? Whhb : Whhf;
    float v = (k < 128) ? Wih[g * 128 + k] : Whh[g * 128 + (k - 128)];
    g_Wt1[((size_t)dir * 256 + k) * GATES + g] = v;
}

__global__ void transpose2_kernel(const float* __restrict__ Wihf, const float* __restrict__ Whhf,
                                  const float* __restrict__ Wihb, const float* __restrict__ Whhb) {
    int g = blockIdx.x, k = threadIdx.x, dir = blockIdx.y;
    const float* Wih = dir ? Wihb : Wihf;
    const float* Whh = dir ? Whhb : Whhf;
    float v = (k < 256) ? Wih[g * 256 + k] : Whh[g * 64 + (k - 256)];
    g_Wt2[((size_t)dir * KTOT2 + k) * GATES2 + g] = v;
}

// ---------------------------------------------------------------------------
// Prep: counting sort of docs by length, DESCENDING (deterministic outputs:
// per-doc results independent of tile composition).
// ---------------------------------------------------------------------------
__global__ void sort_kernel(const int* __restrict__ lens) {
    __shared__ int hist[TSEQ + 1];
    __shared__ int cur[TSEQ + 1];
    int tid = threadIdx.x;
    if (tid <= TSEQ) hist[tid] = 0;
    __syncthreads();
    for (int i = tid; i < TDOCS; i += blockDim.x) atomicAdd(&hist[lens[i]], 1);
    __syncthreads();
    if (tid == 0) {
        int acc = 0;
        for (int l = TSEQ; l >= 1; l--) { cur[l] = acc; acc += hist[l]; }
    }
    __syncthreads();
    for (int i = tid; i < TDOCS; i += blockDim.x) {
        int l = lens[i];
        int p = atomicAdd(&cur[l], 1);
        g_perm[p] = i;
    }
}

// ---------------------------------------------------------------------------
// Layer 1: BiLSTM over docs, mean-pooled. One CTA = 32 docs x 1 direction.
// 512 threads (16 warps, 4/SMSP) for latency hiding at barriers/waits.
// Thread micro-tile: 2 docs x (4 hids x 4 gates), hid-packed f32x2.
// ---------------------------------------------------------------------------
__global__ void __launch_bounds__(NT1, 1)
lstm1_kernel(const float* __restrict__ docs, const int* __restrict__ lens) {
    extern __shared__ float sm[];
    float* xh = sm;                       // [256][32]: k<128 x_t, k>=128 h
    float* cs = sm + 8192;                // [128][32]
    float* ss = sm + 12288;               // [128][32]
    float* wb = sm + 16384;               // [2][KC1][512] double buffer
    int*   Ls  = (int*)(sm + 16384 + 2 * KC1 * GATES);   // [32]
    int*   Did = Ls + TILE1;                              // [32]

    const int tid  = threadIdx.x;
    const int dir  = blockIdx.y;
    const int tile = blockIdx.x;
    const float* Wt = g_Wt1 + (size_t)dir * 256 * GATES;

    if (tid < TILE1) {
        int d = g_perm[tile * TILE1 + tid];
        Did[tid] = d;
        Ls[tid]  = lens[d];
    }
    // zero h-part of xh, c, sum
    for (int i = tid; i < 12288; i += NT1) sm[4096 + i] = 0.f;
    __syncthreads();

    int maxlen = 0;
    #pragma unroll 8
    for (int i = 0; i < TILE1; i++) maxlen = max(maxlen, Ls[i]);

    const int dg = tid & 15;   // doc group: docs 2*dg, 2*dg+1
    const int gq = tid >> 4;   // hid group: hids 4*gq..4*gq+3 (0..31)
    const int xd = tid >> 4;   // x-load: doc 0..31
    const int xj = tid & 15;   // x-load: 8-float slice

    for (int st = 0; st < maxlen; ++st) {
        // issue chunk 0 of W for this step (64 KB, 8 x cp.async16 per thread)
        {
            const float4* src = (const float4*)Wt + tid;
            float4* dst = (float4*)wb + tid;
            #pragma unroll
            for (int q = 0; q < 8; q++) cp_async16(dst + NT1 * q, src + NT1 * q);
            cp_commit();
        }
        // load x_t for each doc (transposed into xh[k][d])
        {
            int L  = Ls[xd];
            int te = (dir == 0) ? st : (L - 1 - st);
            te = min(max(te, 0), TSEQ - 1);
            const float4* row = (const float4*)(docs + ((size_t)Did[xd] * TSEQ + te) * DIM);
            #pragma unroll
            for (int r = 0; r < 2; r++) {
                float4 v = row[xj * 2 + r];
                int k0 = xj * 8 + r * 4;
                xh[(k0 + 0) * TILE1 + xd] = v.x;
                xh[(k0 + 1) * TILE1 + xd] = v.y;
                xh[(k0 + 2) * TILE1 + xd] = v.z;
                xh[(k0 + 3) * TILE1 + xd] = v.w;
            }
        }
        __syncthreads();

        // acc[b][jp][d]: packed {gate(2jp), gate(2jp+1)} for doc d (2 docs)
        unsigned long long acc[4][2][2];
        #pragma unroll
        for (int b = 0; b < 4; b++)
            #pragma unroll
            for (int jp = 0; jp < 2; jp++) { acc[b][jp][0] = 0ull; acc[b][jp][1] = 0ull; }

        // K = 256 in 8 chunks, double-buffered cp.async
        for (int n = 0; n < NCH1; n++) {
            if (n + 1 < NCH1) {
                const float4* src = (const float4*)(Wt + (size_t)(n + 1) * KC1 * GATES) + tid;
                float4* dst = (float4*)(wb + ((n + 1) & 1) * (KC1 * GATES)) + tid;
                #pragma unroll
                for (int q = 0; q < 8; q++) cp_async16(dst + NT1 * q, src + NT1 * q);
                cp_commit();
                cp_wait1();
            } else {
                cp_wait0();
            }
            __syncthreads();

            const float* W  = wb + (n & 1) * (KC1 * GATES);
            const float* xk = xh + n * KC1 * TILE1;
            #pragma unroll 4
            for (int kc = 0; kc < KC1; kc++) {
                float2 xv = *(const float2*)(xk + kc * TILE1 + (dg << 1));
                unsigned long long xp[2] = { dup2(xv.x), dup2(xv.y) };
                #pragma unroll
                for (int b = 0; b < 4; b++) {
                    ulonglong2 wv = *(const ulonglong2*)(W + kc * GATES + b * HID + (gq << 2));
                    ffma2(acc[b][0][0], wv.x, xp[0]);
                    ffma2(acc[b][0][1], wv.x, xp[1]);
                    ffma2(acc[b][1][0], wv.y, xp[0]);
                    ffma2(acc[b][1][1], wv.y, xp[1]);
                }
            }
            __syncthreads();
        }

        // unpack packed gate pairs -> ga[b][j][d]
        float ga[4][4][2];
        #pragma unroll
        for (int b = 0; b < 4; b++)
            #pragma unroll
            for (int jp = 0; jp < 2; jp++)
                #pragma unroll
                for (int d2 = 0; d2 < 2; d2++) {
                    float2 p = unpack2(acc[b][jp][d2]);
                    ga[b][2 * jp + 0][d2] = p.x;
                    ga[b][2 * jp + 1][d2] = p.y;
                }

        // state update: thread owns (4 hids x 2 docs), fully local i/f/g/o
        {
            const int dbase = dg << 1;
            int Lloc[2] = { Ls[dbase], Ls[dbase + 1] };
            #pragma unroll
            for (int j = 0; j < 4; j++) {
                int h = (gq << 2) + j;
                float2 co = *(float2*)(cs + h * TILE1 + dbase);
                float2 ho = *(float2*)(xh + (128 + h) * TILE1 + dbase);
                float2 so = *(float2*)(ss + h * TILE1 + dbase);
                float ca[2] = { co.x, co.y };
                float ha[2] = { ho.x, ho.y };
                float sa[2] = { so.x, so.y };
                #pragma unroll
                for (int d2 = 0; d2 < 2; d2++) {
                    float ig = sigf(ga[0][j][d2]);
                    float fg = sigf(ga[1][j][d2]);
                    float gg = tanh_f(ga[2][j][d2]);
                    float og = sigf(ga[3][j][d2]);
                    float c2v = fmaf(fg, ca[d2], ig * gg);
                    float h2v = og * tanh_f(c2v);
                    if (st < Lloc[d2]) {
                        ca[d2] = c2v;
                        ha[d2] = h2v;
                        sa[d2] += h2v;
                    }
                }
                *(float2*)(cs + h * TILE1 + dbase) = make_float2(ca[0], ca[1]);
                *(float2*)(xh + (128 + h) * TILE1 + dbase) = make_float2(ha[0], ha[1]);
                *(float2*)(ss + h * TILE1 + dbase) = make_float2(sa[0], sa[1]);
            }
        }
        __syncthreads();
    }

    // epilogue: doc_emb[doc][dir*128 + h] = sum / len
    {
        const int dbase = dg << 1;
        #pragma unroll
        for (int j = 0; j < 4; j++) {
            int h = (gq << 2) + j;
            #pragma unroll
            for (int d2 = 0; d2 < 2; d2++) {
                int d = dbase + d2;
                float v = ss[h * TILE1 + d] / (float)Ls[d];
                g_demb[(size_t)Did[d] * 256 + dir * 128 + h] = v;
            }
        }
    }
}

// ---------------------------------------------------------------------------
// Layer 2: BiLSTM over nodes (K<=8 steps, input 256, H2=64) + mask + output.
// One CTA = 8 nodes x 1 direction, 256 threads.
// ---------------------------------------------------------------------------
__global__ void __launch_bounds__(256, 1)
lstm2_kernel(const int* __restrict__ nidx, const int* __restrict__ nlens,
             const int* __restrict__ gnum, float* __restrict__ out) {
    extern __shared__ float sm[];
    float* xh = sm;                 // [320][8]: k<256 x, k>=256 h
    float* cs = sm + 2560;          // [64][8]
    float* ss = sm + 3072;          // [64][8]
    float* wb = sm + 3584;          // [2][KC2][256]
    int*   Ls = (int*)(sm + 3584 + 2 * KC2 * GATES2);    // [8]

    const int tid  = threadIdx.x;
    const int dir  = blockIdx.y;
    const int tile = blockIdx.x;
    const float* Wt = g_Wt2 + (size_t)dir * KTOT2 * GATES2;

    if (tid < TILE2) Ls[tid] = nlens[tile * TILE2 + tid];
    for (int i = tid; i < 1536; i += 256) sm[2048 + i] = 0.f;
    __syncthreads();

    int maxlen = 0;
    #pragma unroll
    for (int i = 0; i < TILE2; i++) maxlen = max(maxlen, Ls[i]);

    const int ng = tid & 3;     // node group: nodes 2*ng, 2*ng+1
    const int hh = tid >> 2;    // hid 0..63
    const int xn = tid >> 5;    // x-gather: node 0..7
    const int xq = tid & 31;    // x-gather: 8-float slice

    for (int st = 0; st < maxlen; ++st) {
        {
            const float4* src = (const float4*)Wt + tid;
            float4* dst = (float4*)wb + tid;
            #pragma unroll
            for (int q = 0; q < 16; q++) cp_async16(dst + 256 * q, src + 256 * q);
            cp_commit();
        }
        {
            int L  = Ls[xn];
            int te = (dir == 0) ? st : (L - 1 - st);
            te = min(max(te, 0), KSTEPS - 1);
            int gn = tile * TILE2 + xn;
            int didx = nidx[gn * KSTEPS + te];
            const float4* row = (const float4*)(g_demb + (size_t)didx * 256);
            #pragma unroll
            for (int r = 0; r < 2; r++) {
                float4 v = row[xq * 2 + r];
                int k0 = xq * 8 + r * 4;
                xh[(k0 + 0) * TILE2 + xn] = v.x;
                xh[(k0 + 1) * TILE2 + xn] = v.y;
                xh[(k0 + 2) * TILE2 + xn] = v.z;
                xh[(k0 + 3) * TILE2 + xn] = v.w;
            }
        }
        __syncthreads();

        unsigned long long acc[4];
        #pragma unroll
        for (int b = 0; b < 4; b++) acc[b] = 0ull;

        for (int n = 0; n < NCH2; n++) {
            if (n + 1 < NCH2) {
                const float4* src = (const float4*)(Wt + (size_t)(n + 1) * KC2 * GATES2) + tid;
                float4* dst = (float4*)(wb + ((n + 1) & 1) * (KC2 * GATES2)) + tid;
                #pragma unroll
                for (int q = 0; q < 16; q++) cp_async16(dst + 256 * q, src + 256 * q);
                cp_commit();
                cp_wait1();
            } else {
                cp_wait0();
            }
            __syncthreads();

            const float* W  = wb + (n & 1) * (KC2 * GATES2);
            const float* xk = xh + n * KC2 * TILE2;
            #pragma unroll 4
            for (int kc = 0; kc < KC2; kc++) {
                unsigned long long xv = *(const unsigned long long*)(xk + kc * TILE2 + (ng << 1));
                #pragma unroll
                for (int b = 0; b < 4; b++) {
                    unsigned long long wp = dup2(W[kc * GATES2 + b * HID2 + hh]);
                    ffma2(acc[b], wp, xv);
                }
            }
            __syncthreads();
        }

        {
            float2 gi2 = unpack2(acc[0]);
            float2 gf2 = unpack2(acc[1]);
            float2 gg2 = unpack2(acc[2]);
            float2 go2 = unpack2(acc[3]);
            float gia[2] = { gi2.x, gi2.y };
            float gfa[2] = { gf2.x, gf2.y };
            float gga[2] = { gg2.x, gg2.y };
            float goa[2] = { go2.x, go2.y };
            #pragma unroll
            for (int e = 0; e < 2; e++) {
                int nd = (ng << 1) + e;
                float co = cs[hh * TILE2 + nd];
                float ho = xh[(256 + hh) * TILE2 + nd];
                float so = ss[hh * TILE2 + nd];
                float ig = sigf(gia[e]);
                float fg = sigf(gfa[e]);
                float gg = tanh_f(gga[e]);
                float og = sigf(goa[e]);
                float c2v = fmaf(fg, co, ig * gg);
                float h2v = og * tanh_f(c2v);
                bool act = st < Ls[nd];
                cs[hh * TILE2 + nd] = act ? c2v : co;
                xh[(256 + hh) * TILE2 + nd] = act ? h2v : ho;
                ss[hh * TILE2 + nd] = act ? (so + h2v) : so;
            }
        }
        __syncthreads();
    }

    {
        #pragma unroll
        for (int e = 0; e < 2; e++) {
            int nd = (ng << 1) + e;
            int gn = tile * TILE2 + nd;
            int gi = gn >> 6;
            int ni = gn & 63;
            float gm = (ni < gnum[gi]) ? 1.f : 0.f;
            float v = ss[hh * TILE2 + nd] / (float)Ls[nd] * gm;
            out[(size_t)gn * 128 + dir * 64 + hh] = v;
            if (dir == 0 && hh == 0) out[NNODES * 128 + gn] = gm;
        }
    }
}

// ---------------------------------------------------------------------------
// Launch
// ---------------------------------------------------------------------------
extern "C" void kernel_launch(void* const* d_in, const int* in_sizes, int n_in,
                              void* d_out, int out_size) {
    const float* docs  = (const float*)d_in[0];
    const int*   dlens = (const int*)  d_in[1];
    const int*   nidx  = (const int*)  d_in[2];
    const int*   nlens = (const int*)  d_in[3];
    const int*   gnum  = (const int*)  d_in[4];
    const float* Wih1f = (const float*)d_in[5];
    const float* Whh1f = (const float*)d_in[6];
    const float* Wih1b = (const float*)d_in[7];
    const float* Whh1b = (const float*)d_in[8];
    const float* Wih2f = (const float*)d_in[9];
    const float* Whh2f = (const float*)d_in[10];
    const float* Wih2b = (const float*)d_in[11];
    const float* Whh2b = (const float*)d_in[12];
    float* out = (float*)d_out;

    const size_t sm1 = (size_t)(16384 + 2 * KC1 * GATES) * 4 + (TILE1 * 2) * 4;    // 196864 B
    const size_t sm2 = (size_t)(3584 + 2 * KC2 * GATES2) * 4 + TILE2 * 4 + 32;     // ~145472 B
    cudaFuncSetAttribute(lstm1_kernel, cudaFuncAttributeMaxDynamicSharedMemorySize, (int)sm1);
    cudaFuncSetAttribute(lstm2_kernel, cudaFuncAttributeMaxDynamicSharedMemorySize, (int)sm2);

    transpose1_kernel<<<dim3(512, 2), 256>>>(Wih1f, Whh1f, Wih1b, Whh1b);
    transpose2_kernel<<<dim3(256, 2), 320>>>(Wih2f, Whh2f, Wih2b, Whh2b);
    sort_kernel<<<1, 1024>>>(dlens);
    lstm1_kernel<<<dim3(TDOCS / TILE1, 2), NT1, sm1>>>(docs, dlens);
    lstm2_kernel<<<dim3(NNODES / TILE2, 2), 256, sm2>>>(nidx, nlens, gnum, out);
    (void)in_sizes; (void)n_in; (void)out_size;
}

// round 9
// speedup vs baseline: 1.0849x; 1.0849x over previous
#include <cuda_runtime.h>
#include <cstdint>

// ---------------------------------------------------------------------------
// Problem constants (fixed by setup_inputs)
// ---------------------------------------------------------------------------
#define TDOCS 4096
#define TSEQ  64
#define DIM   128
#define HID   128
#define GATES 512      // 4*HID
#define TILE1 32       // docs per CTA (layer 1)
#define KC1   32       // k-chunk (layer 1)
#define NCH1  8        // 256 / 32
#define NT1   512      // threads per CTA (layer 1): 16 warps

#define NNODES 512     // G*N = 8*64
#define KSTEPS 8
#define HID2   64
#define GATES2 256     // 4*HID2
#define KTOT2  320     // 256 (x) + 64 (h)
#define TILE2  8
#define KC2    64
#define NCH2   5       // 320 / 64

// ---------------------------------------------------------------------------
// Device scratch (static; no allocations anywhere)
// ---------------------------------------------------------------------------
// Layer-1 weights, gate-interleaved k-major:
//   g_Wt1[((dir*256 + k)*64 + hp)*8 + b*2 + r] = W[gate b, hid 2*hp+r][k]
// so one 32B span holds all 4 gates' packed hid-pairs for (k, hp).
__device__ float g_Wt1[2 * 256 * GATES];      // (1 MB)
__device__ float g_Wt2[2 * KTOT2 * GATES2];   // [dir][k][gate]   (640 KB)
__device__ float g_demb[TDOCS * 256];         // doc embeddings   (4 MB)
__device__ int   g_perm[TDOCS];               // docs sorted by length, desc

// ---------------------------------------------------------------------------
// Helpers
// ---------------------------------------------------------------------------
__device__ __forceinline__ float sigf(float x) {
    return __fdividef(1.f, 1.f + __expf(-x));
}
__device__ __forceinline__ float tanh_f(float x) {
    return fmaf(2.f, __fdividef(1.f, 1.f + __expf(-2.f * x)), -1.f);
}
__device__ __forceinline__ void cp_async16(void* dst_smem, const void* src_gmem) {
    unsigned s = (unsigned)__cvta_generic_to_shared(dst_smem);
    asm volatile("cp.async.ca.shared.global [%0], [%1], 16;\n" :: "r"(s), "l"(src_gmem));
}
__device__ __forceinline__ void cp_commit() { asm volatile("cp.async.commit_group;\n"); }
__device__ __forceinline__ void cp_wait1()  { asm volatile("cp.async.wait_group 1;\n"); }
__device__ __forceinline__ void cp_wait0()  { asm volatile("cp.async.wait_group 0;\n"); }

// Packed fp32x2 (issue-slot compression; fma-pipe cost = 2x FFMA)
__device__ __forceinline__ void ffma2(unsigned long long& d,
                                      unsigned long long a, unsigned long long b) {
    asm("fma.rn.f32x2 %0, %1, %2, %0;" : "+l"(d) : "l"(a), "l"(b));
}
__device__ __forceinline__ unsigned long long dup2(float x) {
    unsigned long long r;
    asm("mov.b64 %0, {%1, %1};" : "=l"(r) : "f"(x));
    return r;
}
__device__ __forceinline__ float2 unpack2(unsigned long long v) {
    float2 r;
    asm("mov.b64 {%0, %1}, %2;" : "=f"(r.x), "=f"(r.y) : "l"(v));
    return r;
}

// ---------------------------------------------------------------------------
// Prep: transposes
// ---------------------------------------------------------------------------
__global__ void transpose1_kernel(const float* __restrict__ Wihf, const float* __restrict__ Whhf,
                                  const float* __restrict__ Wihb, const float* __restrict__ Whhb) {
    int g = blockIdx.x, k = threadIdx.x, dir = blockIdx.y;
    const float* Wih = dir ? Wihb : Wihf;
    const float* Whh = dir ? Whhb : Whhf;
    float v = (k < 128) ? Wih[g * 128 + k] : Whh[g * 128 + (k - 128)];
    int b = g >> 7;          // gate type 0..3
    int hid = g & 127;
    int hp = hid >> 1, r = hid & 1;
    g_Wt1[(((size_t)dir * 256 + k) * 64 + hp) * 8 + b * 2 + r] = v;
}

__global__ void transpose2_kernel(const float* __restrict__ Wihf, const float* __restrict__ Whhf,
                                  const float* __restrict__ Wihb, const float* __restrict__ Whhb) {
    int g = blockIdx.x, k = threadIdx.x, dir = blockIdx.y;
    const float* Wih = dir ? Wihb : Wihf;
    const float* Whh = dir ? Whhb : Whhf;
    float v = (k < 256) ? Wih[g * 256 + k] : Whh[g * 64 + (k - 256)];
    g_Wt2[((size_t)dir * KTOT2 + k) * GATES2 + g] = v;
}

// ---------------------------------------------------------------------------
// Prep: counting sort of docs by length, DESCENDING (deterministic outputs:
// per-doc results independent of tile composition).
// ---------------------------------------------------------------------------
__global__ void sort_kernel(const int* __restrict__ lens) {
    __shared__ int hist[TSEQ + 1];
    __shared__ int cur[TSEQ + 1];
    int tid = threadIdx.x;
    if (tid <= TSEQ) hist[tid] = 0;
    __syncthreads();
    for (int i = tid; i < TDOCS; i += blockDim.x) atomicAdd(&hist[lens[i]], 1);
    __syncthreads();
    if (tid == 0) {
        int acc = 0;
        for (int l = TSEQ; l >= 1; l--) { cur[l] = acc; acc += hist[l]; }
    }
    __syncthreads();
    for (int i = tid; i < TDOCS; i += blockDim.x) {
        int l = lens[i];
        int p = atomicAdd(&cur[l], 1);
        g_perm[p] = i;
    }
}

// ---------------------------------------------------------------------------
// Layer 1: BiLSTM over docs, mean-pooled. One CTA = 32 docs x 1 direction,
// 512 threads (16 warps). Thread micro-tile: 2 hids x 4 gates x 4 docs.
// Gate-interleaved W layout: per kc only 3 LDS.128 (2x W, 1x x) feed 16 FFMA2.
// ---------------------------------------------------------------------------
__global__ void __launch_bounds__(NT1, 1)
lstm1_kernel(const float* __restrict__ docs, const int* __restrict__ lens) {
    extern __shared__ float sm[];
    float* xh = sm;                       // [256][32]: k<128 x_t, k>=128 h
    float* cs = sm + 8192;                // [128][32]
    float* ss = sm + 12288;               // [128][32]
    float* wb = sm + 16384;               // [2][KC1][512] double buffer
    int*   Ls  = (int*)(sm + 16384 + 2 * KC1 * GATES);   // [32]
    int*   Did = Ls + TILE1;                              // [32]

    const int tid  = threadIdx.x;
    const int dir  = blockIdx.y;
    const int tile = blockIdx.x;
    const float* Wt = g_Wt1 + (size_t)dir * 256 * GATES;

    if (tid < TILE1) {
        int d = g_perm[tile * TILE1 + tid];
        Did[tid] = d;
        Ls[tid]  = lens[d];
    }
    for (int i = tid; i < 12288; i += NT1) sm[4096 + i] = 0.f;
    __syncthreads();

    int maxlen = 0;
    #pragma unroll 8
    for (int i = 0; i < TILE1; i++) maxlen = max(maxlen, Ls[i]);

    const int dg = tid & 7;    // doc group: docs 4*dg..4*dg+3
    const int hp = tid >> 3;   // hid pair 0..63 (hids 2*hp, 2*hp+1)
    const int xd = tid >> 4;   // x-load: doc 0..31
    const int xj = tid & 15;   // x-load: 8-float slice

    for (int st = 0; st < maxlen; ++st) {
        // issue chunk 0 of W for this step (64 KB, 8 cp.async16/thread)
        {
            const float4* src = (const float4*)Wt + tid;
            float4* dst = (float4*)wb + tid;
            #pragma unroll
            for (int q = 0; q < 8; q++) cp_async16(dst + NT1 * q, src + NT1 * q);
            cp_commit();
        }
        // load x_t for each doc (transposed into xh[k][d])
        {
            int L  = Ls[xd];
            int te = (dir == 0) ? st : (L - 1 - st);
            te = min(max(te, 0), TSEQ - 1);
            const float4* row = (const float4*)(docs + ((size_t)Did[xd] * TSEQ + te) * DIM);
            #pragma unroll
            for (int r = 0; r < 2; r++) {
                float4 v = row[xj * 2 + r];
                int k0 = xj * 8 + r * 4;
                xh[(k0 + 0) * TILE1 + xd] = v.x;
                xh[(k0 + 1) * TILE1 + xd] = v.y;
                xh[(k0 + 2) * TILE1 + xd] = v.z;
                xh[(k0 + 3) * TILE1 + xd] = v.w;
            }
        }
        __syncthreads();

        // acc[b][d]: packed pair {hid 2hp, hid 2hp+1} for gate b, doc d
        unsigned long long acc[4][4];
        #pragma unroll
        for (int b = 0; b < 4; b++)
            #pragma unroll
            for (int d2 = 0; d2 < 4; d2++) acc[b][d2] = 0ull;

        // K = 256 in 8 chunks, double-buffered cp.async
        for (int n = 0; n < NCH1; n++) {
            if (n + 1 < NCH1) {
                const float4* src = (const float4*)(Wt + (size_t)(n + 1) * KC1 * GATES) + tid;
                float4* dst = (float4*)(wb + ((n + 1) & 1) * (KC1 * GATES)) + tid;
                #pragma unroll
                for (int q = 0; q < 8; q++) cp_async16(dst + NT1 * q, src + NT1 * q);
                cp_commit();
                cp_wait1();
            } else {
                cp_wait0();
            }
            __syncthreads();

            const float* W  = wb + (n & 1) * (KC1 * GATES);
            const float* xk = xh + n * KC1 * TILE1;
            #pragma unroll 4
            for (int kc = 0; kc < KC1; kc++) {
                float4 xv = *(const float4*)(xk + kc * TILE1 + (dg << 2));
                unsigned long long xp[4] = { dup2(xv.x), dup2(xv.y), dup2(xv.z), dup2(xv.w) };
                const float* Wr = W + kc * GATES + hp * 8;
                ulonglong2 w01 = *(const ulonglong2*)(Wr);      // gate0 pair, gate1 pair
                ulonglong2 w23 = *(const ulonglong2*)(Wr + 4);  // gate2 pair, gate3 pair
                #pragma unroll
                for (int d2 = 0; d2 < 4; d2++) {
                    ffma2(acc[0][d2], w01.x, xp[d2]);
                    ffma2(acc[1][d2], w01.y, xp[d2]);
                    ffma2(acc[2][d2], w23.x, xp[d2]);
                    ffma2(acc[3][d2], w23.y, xp[d2]);
                }
            }
            __syncthreads();
        }

        // unpack packed hid pairs -> ga[b][r][d] (r selects hid 2hp+r)
        float ga[4][2][4];
        #pragma unroll
        for (int b = 0; b < 4; b++)
            #pragma unroll
            for (int d2 = 0; d2 < 4; d2++) {
                float2 p = unpack2(acc[b][d2]);
                ga[b][0][d2] = p.x;
                ga[b][1][d2] = p.y;
            }

        // state update: thread owns (2 hids x 4 docs), fully local i/f/g/o
        {
            const int dbase = dg << 2;
            int Lloc[4];
            #pragma unroll
            for (int d2 = 0; d2 < 4; d2++) Lloc[d2] = Ls[dbase + d2];
            #pragma unroll
            for (int r = 0; r < 2; r++) {
                int h = (hp << 1) + r;
                float4 co = *(float4*)(cs + h * TILE1 + dbase);
                float4 ho = *(float4*)(xh + (128 + h) * TILE1 + dbase);
                float4 so = *(float4*)(ss + h * TILE1 + dbase);
                float ca[4] = { co.x, co.y, co.z, co.w };
                float ha[4] = { ho.x, ho.y, ho.z, ho.w };
                float sa[4] = { so.x, so.y, so.z, so.w };
                #pragma unroll
                for (int d2 = 0; d2 < 4; d2++) {
                    float ig = sigf(ga[0][r][d2]);
                    float fg = sigf(ga[1][r][d2]);
                    float gg = tanh_f(ga[2][r][d2]);
                    float og = sigf(ga[3][r][d2]);
                    float c2v = fmaf(fg, ca[d2], ig * gg);
                    float h2v = og * tanh_f(c2v);
                    if (st < Lloc[d2]) {
                        ca[d2] = c2v;
                        ha[d2] = h2v;
                        sa[d2] += h2v;
                    }
                }
                *(float4*)(cs + h * TILE1 + dbase) = make_float4(ca[0], ca[1], ca[2], ca[3]);
                *(float4*)(xh + (128 + h) * TILE1 + dbase) = make_float4(ha[0], ha[1], ha[2], ha[3]);
                *(float4*)(ss + h * TILE1 + dbase) = make_float4(sa[0], sa[1], sa[2], sa[3]);
            }
        }
        __syncthreads();
    }

    // epilogue: doc_emb[doc][dir*128 + h] = sum / len
    {
        const int dbase = dg << 2;
        #pragma unroll
        for (int r = 0; r < 2; r++) {
            int h = (hp << 1) + r;
            #pragma unroll
            for (int d2 = 0; d2 < 4; d2++) {
                int d = dbase + d2;
                float v = ss[h * TILE1 + d] / (float)Ls[d];
                g_demb[(size_t)Did[d] * 256 + dir * 128 + h] = v;
            }
        }
    }
}

// ---------------------------------------------------------------------------
// Layer 2: BiLSTM over nodes (K<=8 steps, input 256, H2=64) + mask + output.
// One CTA = 8 nodes x 1 direction, 256 threads.
// ---------------------------------------------------------------------------
__global__ void __launch_bounds__(256, 1)
lstm2_kernel(const int* __restrict__ nidx, const int* __restrict__ nlens,
             const int* __restrict__ gnum, float* __restrict__ out) {
    extern __shared__ float sm[];
    float* xh = sm;                 // [320][8]: k<256 x, k>=256 h
    float* cs = sm + 2560;          // [64][8]
    float* ss = sm + 3072;          // [64][8]
    float* wb = sm + 3584;          // [2][KC2][256]
    int*   Ls = (int*)(sm + 3584 + 2 * KC2 * GATES2);    // [8]

    const int tid  = threadIdx.x;
    const int dir  = blockIdx.y;
    const int tile = blockIdx.x;
    const float* Wt = g_Wt2 + (size_t)dir * KTOT2 * GATES2;

    if (tid < TILE2) Ls[tid] = nlens[tile * TILE2 + tid];
    for (int i = tid; i < 1536; i += 256) sm[2048 + i] = 0.f;
    __syncthreads();

    int maxlen = 0;
    #pragma unroll
    for (int i = 0; i < TILE2; i++) maxlen = max(maxlen, Ls[i]);

    const int ng = tid & 3;     // node group: nodes 2*ng, 2*ng+1
    const int hh = tid >> 2;    // hid 0..63
    const int xn = tid >> 5;    // x-gather: node 0..7
    const int xq = tid & 31;    // x-gather: 8-float slice

    for (int st = 0; st < maxlen; ++st) {
        {
            const float4* src = (const float4*)Wt + tid;
            float4* dst = (float4*)wb + tid;
            #pragma unroll
            for (int q = 0; q < 16; q++) cp_async16(dst + 256 * q, src + 256 * q);
            cp_commit();
        }
        {
            int L  = Ls[xn];
            int te = (dir == 0) ? st : (L - 1 - st);
            te = min(max(te, 0), KSTEPS - 1);
            int gn = tile * TILE2 + xn;
            int didx = nidx[gn * KSTEPS + te];
            const float4* row = (const float4*)(g_demb + (size_t)didx * 256);
            #pragma unroll
            for (int r = 0; r < 2; r++) {
                float4 v = row[xq * 2 + r];
                int k0 = xq * 8 + r * 4;
                xh[(k0 + 0) * TILE2 + xn] = v.x;
                xh[(k0 + 1) * TILE2 + xn] = v.y;
                xh[(k0 + 2) * TILE2 + xn] = v.z;
                xh[(k0 + 3) * TILE2 + xn] = v.w;
            }
        }
        __syncthreads();

        unsigned long long acc[4];
        #pragma unroll
        for (int b = 0; b < 4; b++) acc[b] = 0ull;

        for (int n = 0; n < NCH2; n++) {
            if (n + 1 < NCH2) {
                const float4* src = (const float4*)(Wt + (size_t)(n + 1) * KC2 * GATES2) + tid;
                float4* dst = (float4*)(wb + ((n + 1) & 1) * (KC2 * GATES2)) + tid;
                #pragma unroll
                for (int q = 0; q < 16; q++) cp_async16(dst + 256 * q, src + 256 * q);
                cp_commit();
                cp_wait1();
            } else {
                cp_wait0();
            }
            __syncthreads();

            const float* W  = wb + (n & 1) * (KC2 * GATES2);
            const float* xk = xh + n * KC2 * TILE2;
            #pragma unroll 4
            for (int kc = 0; kc < KC2; kc++) {
                unsigned long long xv = *(const unsigned long long*)(xk + kc * TILE2 + (ng << 1));
                #pragma unroll
                for (int b = 0; b < 4; b++) {
                    unsigned long long wp = dup2(W[kc * GATES2 + b * HID2 + hh]);
                    ffma2(acc[b], wp, xv);
                }
            }
            __syncthreads();
        }

        {
            float2 gi2 = unpack2(acc[0]);
            float2 gf2 = unpack2(acc[1]);
            float2 gg2 = unpack2(acc[2]);
            float2 go2 = unpack2(acc[3]);
            float gia[2] = { gi2.x, gi2.y };
            float gfa[2] = { gf2.x, gf2.y };
            float gga[2] = { gg2.x, gg2.y };
            float goa[2] = { go2.x, go2.y };
            #pragma unroll
            for (int e = 0; e < 2; e++) {
                int nd = (ng << 1) + e;
                float co = cs[hh * TILE2 + nd];
                float ho = xh[(256 + hh) * TILE2 + nd];
                float so = ss[hh * TILE2 + nd];
                float ig = sigf(gia[e]);
                float fg = sigf(gfa[e]);
                float gg = tanh_f(gga[e]);
                float og = sigf(goa[e]);
                float c2v = fmaf(fg, co, ig * gg);
                float h2v = og * tanh_f(c2v);
                bool act = st < Ls[nd];
                cs[hh * TILE2 + nd] = act ? c2v : co;
                xh[(256 + hh) * TILE2 + nd] = act ? h2v : ho;
                ss[hh * TILE2 + nd] = act ? (so + h2v) : so;
            }
        }
        __syncthreads();
    }

    {
        #pragma unroll
        for (int e = 0; e < 2; e++) {
            int nd = (ng << 1) + e;
            int gn = tile * TILE2 + nd;
            int gi = gn >> 6;
            int ni = gn & 63;
            float gm = (ni < gnum[gi]) ? 1.f : 0.f;
            float v = ss[hh * TILE2 + nd] / (float)Ls[nd] * gm;
            out[(size_t)gn * 128 + dir * 64 + hh] = v;
            if (dir == 0 && hh == 0) out[NNODES * 128 + gn] = gm;
        }
    }
}

// ---------------------------------------------------------------------------
// Launch
// ---------------------------------------------------------------------------
extern "C" void kernel_launch(void* const* d_in, const int* in_sizes, int n_in,
                              void* d_out, int out_size) {
    const float* docs  = (const float*)d_in[0];
    const int*   dlens = (const int*)  d_in[1];
    const int*   nidx  = (const int*)  d_in[2];
    const int*   nlens = (const int*)  d_in[3];
    const int*   gnum  = (const int*)  d_in[4];
    const float* Wih1f = (const float*)d_in[5];
    const float* Whh1f = (const float*)d_in[6];
    const float* Wih1b = (const float*)d_in[7];
    const float* Whh1b = (const float*)d_in[8];
    const float* Wih2f = (const float*)d_in[9];
    const float* Whh2f = (const float*)d_in[10];
    const float* Wih2b = (const float*)d_in[11];
    const float* Whh2b = (const float*)d_in[12];
    float* out = (float*)d_out;

    const size_t sm1 = (size_t)(16384 + 2 * KC1 * GATES) * 4 + (TILE1 * 2) * 4;    // 196864 B
    const size_t sm2 = (size_t)(3584 + 2 * KC2 * GATES2) * 4 + TILE2 * 4 + 32;     // ~145472 B
    cudaFuncSetAttribute(lstm1_kernel, cudaFuncAttributeMaxDynamicSharedMemorySize, (int)sm1);
    cudaFuncSetAttribute(lstm2_kernel, cudaFuncAttributeMaxDynamicSharedMemorySize, (int)sm2);

    transpose1_kernel<<<dim3(512, 2), 256>>>(Wih1f, Whh1f, Wih1b, Whh1b);
    transpose2_kernel<<<dim3(256, 2), 320>>>(Wih2f, Whh2f, Wih2b, Whh2b);
    sort_kernel<<<1, 1024>>>(dlens);
    lstm1_kernel<<<dim3(TDOCS / TILE1, 2), NT1, sm1>>>(docs, dlens);
    lstm2_kernel<<<dim3(NNODES / TILE2, 2), 256, sm2>>>(nidx, nlens, gnum, out);
    (void)in_sizes; (void)n_in; (void)out_size;
}

// round 12
// speedup vs baseline: 1.5412x; 1.4205x over previous
#include <cuda_runtime.h>
#include <cuda_bf16.h>
#include <cstdint>

// ---------------------------------------------------------------------------
// Problem constants
// ---------------------------------------------------------------------------
#define TDOCS 4096
#define TSEQ  64
#define DIM   128
#define HID   128
#define GATES 512
#define TILE1 32       // docs per CTA (layer 1)
#define KCH   16       // k per chunk (layer 1 mma)
#define NCHK  16       // 256 / 16
#define NT1   256      // threads layer 1 (8 warps)

#define NNODES 512
#define KSTEPS 8
#define HID2   64
#define GATES2 256
#define KTOT2  320
#define TILE2  8
#define KC2    64
#define NCH2   5

// Layer-1 W prepped layout: [dir][chunk][half(hi/lo)][n(gate-interleaved)][24 bf16]
//   n = hp*8 + b*2 + r  <->  gate row g = b*128 + 2*hp + r   (b: i,f,g,o)
//   row holds k = chunk*16 .. +15 in elems 0..15; elems 16..23 = pad.
#define WROW_E   24
#define WROW_B   48                       // bytes per n-row
#define WHALF_B  (512 * WROW_B)           // 24576
#define WCHUNK_B (2 * WHALF_B)            // 49152 (hi+lo)

// smem layout (bytes), layer 1
#define XH_PITCH 264                       // bf16 per row (528 B)
#define SM_XHHI  0
#define SM_XHLO  16896                     // 32*264*2
#define SM_GATES 33792                     // 32*520*4 = 66560
#define G_PITCH  520
#define SM_WBUF  100352                    // 2 * 49152 = 98304
#define SM_LS    198656                    // Ls[32], Did[32]
#define SM1_TOTAL 198912

// ---------------------------------------------------------------------------
// Device scratch
// ---------------------------------------------------------------------------
__device__ __nv_bfloat16 g_W1s[2 * NCHK * 2 * 512 * WROW_E];   // 1.5 MB
__device__ float g_Wt2[2 * KTOT2 * GATES2];
__device__ float g_demb[TDOCS * 256];
__device__ int   g_perm[TDOCS];

// ---------------------------------------------------------------------------
// Helpers
// ---------------------------------------------------------------------------
__device__ __forceinline__ float sigf(float x) {
    return __fdividef(1.f, 1.f + __expf(-x));
}
__device__ __forceinline__ float tanh_f(float x) {
    return fmaf(2.f, __fdividef(1.f, 1.f + __expf(-2.f * x)), -1.f);
}
__device__ __forceinline__ unsigned smem_u32(const void* p) {
    return (unsigned)__cvta_generic_to_shared(p);
}
__device__ __forceinline__ void cp_async16(void* dst_smem, const void* src_gmem) {
    unsigned s = smem_u32(dst_smem);
    asm volatile("cp.async.ca.shared.global [%0], [%1], 16;\n" :: "r"(s), "l"(src_gmem));
}
__device__ __forceinline__ void cp_commit() { asm volatile("cp.async.commit_group;\n"); }
__device__ __forceinline__ void cp_wait1()  { asm volatile("cp.async.wait_group 1;\n"); }
__device__ __forceinline__ void cp_wait0()  { asm volatile("cp.async.wait_group 0;\n"); }

__device__ __forceinline__ void ldsm_x4(uint32_t* r, uint32_t addr) {
    asm volatile("ldmatrix.sync.aligned.m8n8.x4.shared.b16 {%0,%1,%2,%3}, [%4];"
                 : "=r"(r[0]), "=r"(r[1]), "=r"(r[2]), "=r"(r[3]) : "r"(addr));
}
__device__ __forceinline__ void mma_bf16(float* c, const uint32_t* a, uint32_t b0, uint32_t b1) {
    asm volatile("mma.sync.aligned.m16n8k16.row.col.f32.bf16.bf16.f32 "
                 "{%0,%1,%2,%3}, {%4,%5,%6,%7}, {%8,%9}, {%0,%1,%2,%3};"
                 : "+f"(c[0]), "+f"(c[1]), "+f"(c[2]), "+f"(c[3])
                 : "r"(a[0]), "r"(a[1]), "r"(a[2]), "r"(a[3]), "r"(b0), "r"(b1));
}

// ---------------------------------------------------------------------------
// Prep: layer-1 W -> bf16 hi/lo, gate-interleaved n, chunked + padded rows
// ---------------------------------------------------------------------------
__global__ void prep_w1_kernel(const float* __restrict__ Wihf, const float* __restrict__ Whhf,
                               const float* __restrict__ Wihb, const float* __restrict__ Whhb) {
    int n = threadIdx.x;         // 0..511 interleaved gate index
    int c = blockIdx.x;          // chunk 0..15
    int dir = blockIdx.y;
    const float* Wih = dir ? Wihb : Wihf;
    const float* Whh = dir ? Whhb : Whhf;
    int hp = n >> 3, b = (n >> 1) & 3, r = n & 1;
    int g = b * 128 + hp * 2 + r;
    size_t bh = (((size_t)(dir * NCHK + c) * 2 + 0) * 512 + n) * WROW_E;
    size_t bl = (((size_t)(dir * NCHK + c) * 2 + 1) * 512 + n) * WROW_E;
    for (int kk = 0; kk < KCH; kk++) {
        int k = c * KCH + kk;
        float w = (k < 128) ? Wih[g * 128 + k] : Whh[g * 128 + (k - 128)];
        __nv_bfloat16 hi = __float2bfloat16_rn(w);
        float res = w - __bfloat162float(hi);
        g_W1s[bh + kk] = hi;
        g_W1s[bl + kk] = __float2bfloat16_rn(res);
    }
    for (int kk = KCH; kk < WROW_E; kk++) {   // zero pad
        g_W1s[bh + kk] = __float2bfloat16_rn(0.f);
        g_W1s[bl + kk] = __float2bfloat16_rn(0.f);
    }
}

__global__ void transpose2_kernel(const float* __restrict__ Wihf, const float* __restrict__ Whhf,
                                  const float* __restrict__ Wihb, const float* __restrict__ Whhb) {
    int g = blockIdx.x, k = threadIdx.x, dir = blockIdx.y;
    const float* Wih = dir ? Wihb : Wihf;
    const float* Whh = dir ? Whhb : Whhf;
    float v = (k < 256) ? Wih[g * 256 + k] : Whh[g * 64 + (k - 256)];
    g_Wt2[((size_t)dir * KTOT2 + k) * GATES2 + g] = v;
}

__global__ void sort_kernel(const int* __restrict__ lens) {
    __shared__ int hist[TSEQ + 1];
    __shared__ int cur[TSEQ + 1];
    int tid = threadIdx.x;
    if (tid <= TSEQ) hist[tid] = 0;
    __syncthreads();
    for (int i = tid; i < TDOCS; i += blockDim.x) atomicAdd(&hist[lens[i]], 1);
    __syncthreads();
    if (tid == 0) {
        int acc = 0;
        for (int l = TSEQ; l >= 1; l--) { cur[l] = acc; acc += hist[l]; }
    }
    __syncthreads();
    for (int i = tid; i < TDOCS; i += blockDim.x) {
        int l = lens[i];
        int p = atomicAdd(&cur[l], 1);
        g_perm[p] = i;
    }
}

// ---------------------------------------------------------------------------
// Layer 1: BiLSTM via mma.sync bf16 3-term split. CTA = 32 docs x 1 dir.
// Step: XH[32][256] (bf16 hi/lo) @ W[256][512] -> gates[32][512] fp32.
// Warp w owns N range [w*64, w*64+64). M tiles: 2x16 docs. K: 16 chunks of 16.
// ---------------------------------------------------------------------------
__global__ void __launch_bounds__(NT1, 1)
lstm1_kernel(const float* __restrict__ docs, const int* __restrict__ lens) {
    extern __shared__ char smc[];
    __nv_bfloat16* xh_hi = (__nv_bfloat16*)(smc + SM_XHHI);
    __nv_bfloat16* xh_lo = (__nv_bfloat16*)(smc + SM_XHLO);
    float* gates = (float*)(smc + SM_GATES);
    char*  wbuf  = smc + SM_WBUF;
    int*   Ls    = (int*)(smc + SM_LS);
    int*   Did   = Ls + TILE1;

    const int tid  = threadIdx.x;
    const int dir  = blockIdx.y;
    const int tile = blockIdx.x;
    const char* Wg = (const char*)g_W1s + (size_t)dir * NCHK * WCHUNK_B;

    if (tid < TILE1) {
        int d = g_perm[tile * TILE1 + tid];
        Did[tid] = d;
        Ls[tid]  = lens[d];
    }
    // zero both XH buffers (h region needs 0; x region overwritten each step)
    {
        uint32_t* z = (uint32_t*)smc;
        for (int i = tid; i < 8448; i += NT1) z[i] = 0u;
    }
    __syncthreads();

    int maxlen = 0;
    #pragma unroll 8
    for (int i = 0; i < TILE1; i++) maxlen = max(maxlen, Ls[i]);

    const int wid  = tid >> 5;
    const int lane = tid & 31;
    const int g4   = lane >> 2;   // groupID
    const int t4   = lane & 3;    // threadID in group

    // A ldmatrix addresses (row-major XH, pitch 528B):
    const uint32_t xhh_s = smem_u32(xh_hi);
    const uint32_t xhl_s = smem_u32(xh_lo);
    const uint32_t wb_s  = smem_u32(wbuf);
    const uint32_t aoff  = (uint32_t)(lane & 15) * 528u + (uint32_t)(lane >> 4) * 16u;
    // B ldmatrix: x4 covers an n-tile pair (16 n rows x 16 k)
    const uint32_t brow  = (uint32_t)(wid * 64 + (lane & 7) + ((lane >> 4) << 3)) * WROW_B
                         + (uint32_t)((lane >> 3) & 1) * 16u;

    // state-update ownership: one doc, 8 hid-pairs per thread
    const int ud  = tid >> 3;          // doc 0..31
    const int uh0 = (tid & 7) * 8;     // hp base
    const int Lme = Ls[ud];
    float creg[16], sreg[16];
    #pragma unroll
    for (int s = 0; s < 16; s++) { creg[s] = 0.f; sreg[s] = 0.f; }

    const int xd = tid >> 3;   // x-load doc
    const int xs = tid & 7;    // x-load slice (16 floats)

    for (int st = 0; st < maxlen; ++st) {
        // issue W chunk 0 (49152 B -> 12 cp.async16 per thread)
        {
            const char* src = Wg + tid * 16;
            char* dst = wbuf + tid * 16;
            #pragma unroll
            for (int q = 0; q < 12; q++) cp_async16(dst + q * 4096, src + q * 4096);
            cp_commit();
        }
        // x_t load, split to bf16 hi/lo, store row-major into XH
        {
            int L  = Ls[xd];
            int tt = (dir == 0) ? st : (L - 1 - st);
            tt = min(max(tt, 0), TSEQ - 1);
            const float4* row = (const float4*)(docs + ((size_t)Did[xd] * TSEQ + tt) * DIM);
            #pragma unroll
            for (int r = 0; r < 4; r++) {
                float4 v = row[xs * 4 + r];
                int c0 = xs * 16 + r * 4;
                __nv_bfloat162 h0 = __floats2bfloat162_rn(v.x, v.y);
                __nv_bfloat162 h1 = __floats2bfloat162_rn(v.z, v.w);
                float e0 = v.x - __bfloat162float(__low2bfloat16(h0));
                float e1 = v.y - __bfloat162float(__high2bfloat16(h0));
                float e2 = v.z - __bfloat162float(__low2bfloat16(h1));
                float e3 = v.w - __bfloat162float(__high2bfloat16(h1));
                __nv_bfloat162 l0 = __floats2bfloat162_rn(e0, e1);
                __nv_bfloat162 l1 = __floats2bfloat162_rn(e2, e3);
                *(__nv_bfloat162*)(xh_hi + xd * XH_PITCH + c0)     = h0;
                *(__nv_bfloat162*)(xh_hi + xd * XH_PITCH + c0 + 2) = h1;
                *(__nv_bfloat162*)(xh_lo + xd * XH_PITCH + c0)     = l0;
                *(__nv_bfloat162*)(xh_lo + xd * XH_PITCH + c0 + 2) = l1;
            }
        }
        __syncthreads();

        float acc[2][8][4];
        #pragma unroll
        for (int mt = 0; mt < 2; mt++)
            #pragma unroll
            for (int nt = 0; nt < 8; nt++)
                #pragma unroll
                for (int e = 0; e < 4; e++) acc[mt][nt][e] = 0.f;

        for (int n = 0; n < NCHK; n++) {
            if (n + 1 < NCHK) {
                const char* src = Wg + (size_t)(n + 1) * WCHUNK_B + tid * 16;
                char* dst = wbuf + ((n + 1) & 1) * WCHUNK_B + tid * 16;
                #pragma unroll
                for (int q = 0; q < 12; q++) cp_async16(dst + q * 4096, src + q * 4096);
                cp_commit();
                cp_wait1();
            } else {
                cp_wait0();
            }
            __syncthreads();

            const uint32_t co = (uint32_t)n * 32u;   // k-chunk byte offset in XH row
            uint32_t ah[2][4], al[2][4];
            ldsm_x4(ah[0], xhh_s + aoff + co);
            ldsm_x4(ah[1], xhh_s + 16u * 528u + aoff + co);
            ldsm_x4(al[0], xhl_s + aoff + co);
            ldsm_x4(al[1], xhl_s + 16u * 528u + aoff + co);

            const uint32_t wc = wb_s + (uint32_t)(n & 1) * WCHUNK_B;
            #pragma unroll
            for (int p = 0; p < 4; p++) {
                uint32_t bh[4], bl[4];
                ldsm_x4(bh, wc + brow + (uint32_t)p * 16u * WROW_B);
                ldsm_x4(bl, wc + WHALF_B + brow + (uint32_t)p * 16u * WROW_B);
                #pragma unroll
                for (int mt = 0; mt < 2; mt++) {
                    mma_bf16(acc[mt][2 * p],     ah[mt], bh[0], bh[1]);
                    mma_bf16(acc[mt][2 * p],     al[mt], bh[0], bh[1]);
                    mma_bf16(acc[mt][2 * p],     ah[mt], bl[0], bl[1]);
                    mma_bf16(acc[mt][2 * p + 1], ah[mt], bh[2], bh[3]);
                    mma_bf16(acc[mt][2 * p + 1], al[mt], bh[2], bh[3]);
                    mma_bf16(acc[mt][2 * p + 1], ah[mt], bl[2], bl[3]);
                }
            }
            __syncthreads();
        }

        // C fragments -> gates smem [doc][n] (pitch 520 fp32)
        #pragma unroll
        for (int mt = 0; mt < 2; mt++)
            #pragma unroll
            for (int nt = 0; nt < 8; nt++) {
                int col = wid * 64 + nt * 8 + 2 * t4;
                *(float2*)(gates + (mt * 16 + g4) * G_PITCH + col) =
                    make_float2(acc[mt][nt][0], acc[mt][nt][1]);
                *(float2*)(gates + (mt * 16 + g4 + 8) * G_PITCH + col) =
                    make_float2(acc[mt][nt][2], acc[mt][nt][3]);
            }
        __syncthreads();

        // state update: thread owns (doc ud, hps uh0..uh0+7)
        if (st < Lme) {
            #pragma unroll
            for (int i = 0; i < 8; i++) {
                int hp = uh0 + i;
                float4 ga = *(float4*)(gates + ud * G_PITCH + hp * 8);      // i_e i_o f_e f_o
                float4 gb = *(float4*)(gates + ud * G_PITCH + hp * 8 + 4);  // g_e g_o o_e o_o
                float hn0, hn1;
                {
                    int s = i * 2;
                    float ig = sigf(ga.x), fg = sigf(ga.z), gg = tanh_f(gb.x), og = sigf(gb.z);
                    float c2 = fmaf(fg, creg[s], ig * gg);
                    hn0 = og * tanh_f(c2);
                    creg[s] = c2; sreg[s] += hn0;
                }
                {
                    int s = i * 2 + 1;
                    float ig = sigf(ga.y), fg = sigf(ga.w), gg = tanh_f(gb.y), og = sigf(gb.w);
                    float c2 = fmaf(fg, creg[s], ig * gg);
                    hn1 = og * tanh_f(c2);
                    creg[s] = c2; sreg[s] += hn1;
                }
                __nv_bfloat162 hh = __floats2bfloat162_rn(hn0, hn1);
                float e0 = hn0 - __bfloat162float(__low2bfloat16(hh));
                float e1 = hn1 - __bfloat162float(__high2bfloat16(hh));
                __nv_bfloat162 hl = __floats2bfloat162_rn(e0, e1);
                *(__nv_bfloat162*)(xh_hi + ud * XH_PITCH + 128 + hp * 2) = hh;
                *(__nv_bfloat162*)(xh_lo + ud * XH_PITCH + 128 + hp * 2) = hl;
            }
        }
        __syncthreads();
    }

    // epilogue: mean-pooled embedding
    {
        float inv = 1.f / (float)Lme;
        #pragma unroll
        for (int i = 0; i < 8; i++) {
            int hp = uh0 + i;
            g_demb[(size_t)Did[ud] * 256 + dir * 128 + hp * 2]     = sreg[i * 2] * inv;
            g_demb[(size_t)Did[ud] * 256 + dir * 128 + hp * 2 + 1] = sreg[i * 2 + 1] * inv;
        }
    }
}

// ---------------------------------------------------------------------------
// Layer 2: unchanged SIMT f32x2 path (proven; ~50us)
// ---------------------------------------------------------------------------
__device__ __forceinline__ void ffma2(unsigned long long& d,
                                      unsigned long long a, unsigned long long b) {
    asm("fma.rn.f32x2 %0, %1, %2, %0;" : "+l"(d) : "l"(a), "l"(b));
}
__device__ __forceinline__ unsigned long long dup2(float x) {
    unsigned long long r;
    asm("mov.b64 %0, {%1, %1};" : "=l"(r) : "f"(x));
    return r;
}
__device__ __forceinline__ float2 unpack2(unsigned long long v) {
    float2 r;
    asm("mov.b64 {%0, %1}, %2;" : "=f"(r.x), "=f"(r.y) : "l"(v));
    return r;
}

__global__ void __launch_bounds__(256, 1)
lstm2_kernel(const int* __restrict__ nidx, const int* __restrict__ nlens,
             const int* __restrict__ gnum, float* __restrict__ out) {
    extern __shared__ float sm[];
    float* xh = sm;
    float* cs = sm + 2560;
    float* ss = sm + 3072;
    float* wb = sm + 3584;
    int*   Ls = (int*)(sm + 3584 + 2 * KC2 * GATES2);

    const int tid  = threadIdx.x;
    const int dir  = blockIdx.y;
    const int tile = blockIdx.x;
    const float* Wt = g_Wt2 + (size_t)dir * KTOT2 * GATES2;

    if (tid < TILE2) Ls[tid] = nlens[tile * TILE2 + tid];
    for (int i = tid; i < 1536; i += 256) sm[2048 + i] = 0.f;
    __syncthreads();

    int maxlen = 0;
    #pragma unroll
    for (int i = 0; i < TILE2; i++) maxlen = max(maxlen, Ls[i]);

    const int ng = tid & 3;
    const int hh = tid >> 2;
    const int xn = tid >> 5;
    const int xq = tid & 31;

    for (int st = 0; st < maxlen; ++st) {
        {
            const float4* src = (const float4*)Wt + tid;
            float4* dst = (float4*)wb + tid;
            #pragma unroll
            for (int q = 0; q < 16; q++) cp_async16(dst + 256 * q, src + 256 * q);
            cp_commit();
        }
        {
            int L  = Ls[xn];
            int te = (dir == 0) ? st : (L - 1 - st);
            te = min(max(te, 0), KSTEPS - 1);
            int gn = tile * TILE2 + xn;
            int didx = nidx[gn * KSTEPS + te];
            const float4* row = (const float4*)(g_demb + (size_t)didx * 256);
            #pragma unroll
            for (int r = 0; r < 2; r++) {
                float4 v = row[xq * 2 + r];
                int k0 = xq * 8 + r * 4;
                xh[(k0 + 0) * TILE2 + xn] = v.x;
                xh[(k0 + 1) * TILE2 + xn] = v.y;
                xh[(k0 + 2) * TILE2 + xn] = v.z;
                xh[(k0 + 3) * TILE2 + xn] = v.w;
            }
        }
        __syncthreads();

        unsigned long long acc[4];
        #pragma unroll
        for (int b = 0; b < 4; b++) acc[b] = 0ull;

        for (int n = 0; n < NCH2; n++) {
            if (n + 1 < NCH2) {
                const float4* src = (const float4*)(Wt + (size_t)(n + 1) * KC2 * GATES2) + tid;
                float4* dst = (float4*)(wb + ((n + 1) & 1) * (KC2 * GATES2)) + tid;
                #pragma unroll
                for (int q = 0; q < 16; q++) cp_async16(dst + 256 * q, src + 256 * q);
                cp_commit();
                cp_wait1();
            } else {
                cp_wait0();
            }
            __syncthreads();

            const float* W  = wb + (n & 1) * (KC2 * GATES2);
            const float* xk = xh + n * KC2 * TILE2;
            #pragma unroll 4
            for (int kc = 0; kc < KC2; kc++) {
                unsigned long long xv = *(const unsigned long long*)(xk + kc * TILE2 + (ng << 1));
                #pragma unroll
                for (int b = 0; b < 4; b++) {
                    unsigned long long wp = dup2(W[kc * GATES2 + b * HID2 + hh]);
                    ffma2(acc[b], wp, xv);
                }
            }
            __syncthreads();
        }

        {
            float2 gi2 = unpack2(acc[0]);
            float2 gf2 = unpack2(acc[1]);
            float2 gg2 = unpack2(acc[2]);
            float2 go2 = unpack2(acc[3]);
            float gia[2] = { gi2.x, gi2.y };
            float gfa[2] = { gf2.x, gf2.y };
            float gga[2] = { gg2.x, gg2.y };
            float goa[2] = { go2.x, go2.y };
            #pragma unroll
            for (int e = 0; e < 2; e++) {
                int nd = (ng << 1) + e;
                float co = cs[hh * TILE2 + nd];
                float ho = xh[(256 + hh) * TILE2 + nd];
                float so = ss[hh * TILE2 + nd];
                float ig = sigf(gia[e]);
                float fg = sigf(gfa[e]);
                float gg = tanh_f(gga[e]);
                float og = sigf(goa[e]);
                float c2v = fmaf(fg, co, ig * gg);
                float h2v = og * tanh_f(c2v);
                bool act = st < Ls[nd];
                cs[hh * TILE2 + nd] = act ? c2v : co;
                xh[(256 + hh) * TILE2 + nd] = act ? h2v : ho;
                ss[hh * TILE2 + nd] = act ? (so + h2v) : so;
            }
        }
        __syncthreads();
    }

    {
        #pragma unroll
        for (int e = 0; e < 2; e++) {
            int nd = (ng << 1) + e;
            int gn = tile * TILE2 + nd;
            int gi = gn >> 6;
            int ni = gn & 63;
            float gm = (ni < gnum[gi]) ? 1.f : 0.f;
            float v = ss[hh * TILE2 + nd] / (float)Ls[nd] * gm;
            out[(size_t)gn * 128 + dir * 64 + hh] = v;
            if (dir == 0 && hh == 0) out[NNODES * 128 + gn] = gm;
        }
    }
}

// ---------------------------------------------------------------------------
// Launch
// ---------------------------------------------------------------------------
extern "C" void kernel_launch(void* const* d_in, const int* in_sizes, int n_in,
                              void* d_out, int out_size) {
    const float* docs  = (const float*)d_in[0];
    const int*   dlens = (const int*)  d_in[1];
    const int*   nidx  = (const int*)  d_in[2];
    const int*   nlens = (const int*)  d_in[3];
    const int*   gnum  = (const int*)  d_in[4];
    const float* Wih1f = (const float*)d_in[5];
    const float* Whh1f = (const float*)d_in[6];
    const float* Wih1b = (const float*)d_in[7];
    const float* Whh1b = (const float*)d_in[8];
    const float* Wih2f = (const float*)d_in[9];
    const float* Whh2f = (const float*)d_in[10];
    const float* Wih2b = (const float*)d_in[11];
    const float* Whh2b = (const float*)d_in[12];
    float* out = (float*)d_out;

    const size_t sm1 = SM1_TOTAL;                                               // 198912 B
    const size_t sm2 = (size_t)(3584 + 2 * KC2 * GATES2) * 4 + TILE2 * 4 + 32;  // ~145 KB
    cudaFuncSetAttribute(lstm1_kernel, cudaFuncAttributeMaxDynamicSharedMemorySize, (int)sm1);
    cudaFuncSetAttribute(lstm2_kernel, cudaFuncAttributeMaxDynamicSharedMemorySize, (int)sm2);

    prep_w1_kernel<<<dim3(NCHK, 2), 512>>>(Wih1f, Whh1f, Wih1b, Whh1b);
    transpose2_kernel<<<dim3(256, 2), 320>>>(Wih2f, Whh2f, Wih2b, Whh2b);
    sort_kernel<<<1, 1024>>>(dlens);
    lstm1_kernel<<<dim3(TDOCS / TILE1, 2), NT1, sm1>>>(docs, dlens);
    lstm2_kernel<<<dim3(NNODES / TILE2, 2), 256, sm2>>>(nidx, nlens, gnum, out);
    (void)in_sizes; (void)n_in; (void)out_size;
}

// round 15
// speedup vs baseline: 1.7465x; 1.1332x over previous
#include <cuda_runtime.h>
#include <cuda_bf16.h>
#include <cstdint>

// ---------------------------------------------------------------------------
// Problem constants
// ---------------------------------------------------------------------------
#define TDOCS 4096
#define TSEQ  64
#define DIM   128
#define HID   128
#define GATES 512
#define TILE1 32       // docs per CTA tile (layer 1)
#define KCH   16       // k per chunk (layer 1 mma)
#define NCHK  16       // 256 / 16
#define NT1   256      // threads layer 1 (8 warps)
#define NPAIR 64       // tile pairs: CTA p runs tiles p and 127-p

#define NNODES 512
#define KSTEPS 8
#define HID2   64
#define GATES2 256
#define KTOT2  320
#define TILE2  8
#define KC2    64
#define NCH2   5

// Layer-1 W prepped layout: [dir][chunk][half(hi/lo)][n(gate-interleaved)][24 bf16]
//   n = hp*8 + b*2 + r  <->  gate row g = b*128 + 2*hp + r   (b: i,f,g,o)
#define WROW_E   24
#define WROW_B   48
#define WHALF_B  (512 * WROW_B)           // 24576
#define WCHUNK_B (2 * WHALF_B)            // 49152 (hi+lo)
#define NSTAGE   3

// smem layout (bytes), layer 1
#define XH_PITCH 264                       // bf16 per row (528 B)
#define SM_XHHI  0
#define SM_XHLO  16896                     // 32*264*2
#define SM_WST   33792                     // 3 stages x 49152 = 147456
#define G_PITCH  520                       // gates aliased onto W stages
#define SM_LS    181248                    // Ls[32], Did[32]
#define SM1_TOTAL 181504

// ---------------------------------------------------------------------------
// Device scratch
// ---------------------------------------------------------------------------
__device__ __nv_bfloat16 g_W1s[2 * NCHK * 2 * 512 * WROW_E];   // 1.5 MB
__device__ float g_Wt2[2 * KTOT2 * GATES2];
__device__ float g_demb[TDOCS * 256];
__device__ int   g_perm[TDOCS];

// ---------------------------------------------------------------------------
// Helpers
// ---------------------------------------------------------------------------
__device__ __forceinline__ float sigf(float x) {
    return __fdividef(1.f, 1.f + __expf(-x));
}
__device__ __forceinline__ float tanh_f(float x) {
    return fmaf(2.f, __fdividef(1.f, 1.f + __expf(-2.f * x)), -1.f);
}
__device__ __forceinline__ unsigned smem_u32(const void* p) {
    return (unsigned)__cvta_generic_to_shared(p);
}
__device__ __forceinline__ void cp_async16(void* dst_smem, const void* src_gmem) {
    unsigned s = smem_u32(dst_smem);
    asm volatile("cp.async.ca.shared.global [%0], [%1], 16;\n" :: "r"(s), "l"(src_gmem));
}
__device__ __forceinline__ void cp_commit() { asm volatile("cp.async.commit_group;\n"); }
__device__ __forceinline__ void cp_wait1()  { asm volatile("cp.async.wait_group 1;\n"); }
__device__ __forceinline__ void cp_wait0()  { asm volatile("cp.async.wait_group 0;\n"); }

__device__ __forceinline__ void ldsm_x4(uint32_t* r, uint32_t addr) {
    asm volatile("ldmatrix.sync.aligned.m8n8.x4.shared.b16 {%0,%1,%2,%3}, [%4];"
                 : "=r"(r[0]), "=r"(r[1]), "=r"(r[2]), "=r"(r[3]) : "r"(addr));
}
__device__ __forceinline__ void mma_bf16(float* c, const uint32_t* a, uint32_t b0, uint32_t b1) {
    asm volatile("mma.sync.aligned.m16n8k16.row.col.f32.bf16.bf16.f32 "
                 "{%0,%1,%2,%3}, {%4,%5,%6,%7}, {%8,%9}, {%0,%1,%2,%3};"
                 : "+f"(c[0]), "+f"(c[1]), "+f"(c[2]), "+f"(c[3])
                 : "r"(a[0]), "r"(a[1]), "r"(a[2]), "r"(a[3]), "r"(b0), "r"(b1));
}

// ---------------------------------------------------------------------------
// Prep kernels
// ---------------------------------------------------------------------------
__global__ void prep_w1_kernel(const float* __restrict__ Wihf, const float* __restrict__ Whhf,
                               const float* __restrict__ Wihb, const float* __restrict__ Whhb) {
    int n = threadIdx.x;
    int c = blockIdx.x;
    int dir = blockIdx.y;
    const float* Wih = dir ? Wihb : Wihf;
    const float* Whh = dir ? Whhb : Whhf;
    int hp = n >> 3, b = (n >> 1) & 3, r = n & 1;
    int g = b * 128 + hp * 2 + r;
    size_t bh = (((size_t)(dir * NCHK + c) * 2 + 0) * 512 + n) * WROW_E;
    size_t bl = (((size_t)(dir * NCHK + c) * 2 + 1) * 512 + n) * WROW_E;
    for (int kk = 0; kk < KCH; kk++) {
        int k = c * KCH + kk;
        float w = (k < 128) ? Wih[g * 128 + k] : Whh[g * 128 + (k - 128)];
        __nv_bfloat16 hi = __float2bfloat16_rn(w);
        float res = w - __bfloat162float(hi);
        g_W1s[bh + kk] = hi;
        g_W1s[bl + kk] = __float2bfloat16_rn(res);
    }
    for (int kk = KCH; kk < WROW_E; kk++) {
        g_W1s[bh + kk] = __float2bfloat16_rn(0.f);
        g_W1s[bl + kk] = __float2bfloat16_rn(0.f);
    }
}

__global__ void transpose2_kernel(const float* __restrict__ Wihf, const float* __restrict__ Whhf,
                                  const float* __restrict__ Wihb, const float* __restrict__ Whhb) {
    int g = blockIdx.x, k = threadIdx.x, dir = blockIdx.y;
    const float* Wih = dir ? Wihb : Wihf;
    const float* Whh = dir ? Whhb : Whhf;
    float v = (k < 256) ? Wih[g * 256 + k] : Whh[g * 64 + (k - 256)];
    g_Wt2[((size_t)dir * KTOT2 + k) * GATES2 + g] = v;
}

__global__ void sort_kernel(const int* __restrict__ lens) {
    __shared__ int hist[TSEQ + 1];
    __shared__ int cur[TSEQ + 1];
    int tid = threadIdx.x;
    if (tid <= TSEQ) hist[tid] = 0;
    __syncthreads();
    for (int i = tid; i < TDOCS; i += blockDim.x) atomicAdd(&hist[lens[i]], 1);
    __syncthreads();
    if (tid == 0) {
        int acc = 0;
        for (int l = TSEQ; l >= 1; l--) { cur[l] = acc; acc += hist[l]; }
    }
    __syncthreads();
    for (int i = tid; i < TDOCS; i += blockDim.x) {
        int l = lens[i];
        int p = atomicAdd(&cur[l], 1);
        g_perm[p] = i;
    }
}

// ---------------------------------------------------------------------------
// Layer 1: BiLSTM via mma.sync bf16 3-term split.
// CTA = pair of sorted 32-doc tiles (p, 127-p) x 1 dir -> 128 balanced CTAs.
// 3-stage cp.async W pipeline, ONE barrier per chunk. gates smem aliases the
// W-stage region (gates only live after the chunk loop; W stages dead then).
// ---------------------------------------------------------------------------
__global__ void __launch_bounds__(NT1, 1)
lstm1_kernel(const float* __restrict__ docs, const int* __restrict__ lens) {
    extern __shared__ char smc[];
    __nv_bfloat16* xh_hi = (__nv_bfloat16*)(smc + SM_XHHI);
    __nv_bfloat16* xh_lo = (__nv_bfloat16*)(smc + SM_XHLO);
    char*  wst   = smc + SM_WST;                 // 3 stages of 49152 B
    float* gates = (float*)(smc + SM_WST);       // ALIAS: valid only post-loop
    int*   Ls    = (int*)(smc + SM_LS);
    int*   Did   = Ls + TILE1;

    const int tid  = threadIdx.x;
    const int dir  = blockIdx.y;
    const int pairid = blockIdx.x;
    const char* Wg = (const char*)g_W1s + (size_t)dir * NCHK * WCHUNK_B;

    const int wid  = tid >> 5;
    const int lane = tid & 31;
    const int g4   = lane >> 2;
    const int t4   = lane & 3;

    const uint32_t xhh_s = smem_u32(xh_hi);
    const uint32_t xhl_s = smem_u32(xh_lo);
    const uint32_t wst_s = smem_u32(wst);
    const uint32_t aoff  = (uint32_t)(lane & 15) * 528u + (uint32_t)(lane >> 4) * 16u;
    const uint32_t brow  = (uint32_t)(wid * 64 + (lane & 7) + ((lane >> 4) << 3)) * WROW_B
                         + (uint32_t)((lane >> 3) & 1) * 16u;

    const int ud  = tid >> 3;          // update doc 0..31
    const int uh0 = (tid & 7) * 8;     // update hp base
    const int xd  = tid >> 3;          // x-load doc
    const int xs  = tid & 7;           // x-load slice (16 floats)

    for (int half = 0; half < 2; half++) {
        const int tile = half ? (2 * NPAIR - 1 - pairid) : pairid;

        __syncthreads();   // previous half fully done before smem reinit
        if (tid < TILE1) {
            int d = g_perm[tile * TILE1 + tid];
            Did[tid] = d;
            Ls[tid]  = lens[d];
        }
        // zero XH hi+lo (h region must be 0; x region overwritten per step)
        {
            uint32_t* z = (uint32_t*)smc;
            for (int i = tid; i < 8448; i += NT1) z[i] = 0u;
        }
        __syncthreads();

        int maxlen = 0;
        #pragma unroll 8
        for (int i = 0; i < TILE1; i++) maxlen = max(maxlen, Ls[i]);

        const int Lme = Ls[ud];
        float creg[16], sreg[16];
        #pragma unroll
        for (int s = 0; s < 16; s++) { creg[s] = 0.f; sreg[s] = 0.f; }

        for (int st = 0; st < maxlen; ++st) {
            // issue W chunk 0 -> stage 0 (safe: post end-of-step barrier)
            {
                const char* src = Wg + tid * 16;
                char* dst = wst + tid * 16;
                #pragma unroll
                for (int q = 0; q < 12; q++) cp_async16(dst + q * 4096, src + q * 4096);
                cp_commit();
            }
            // x_t load, split to bf16 hi/lo, store row-major into XH
            {
                int L  = Ls[xd];
                int tt = (dir == 0) ? st : (L - 1 - st);
                tt = min(max(tt, 0), TSEQ - 1);
                const float4* row = (const float4*)(docs + ((size_t)Did[xd] * TSEQ + tt) * DIM);
                #pragma unroll
                for (int r = 0; r < 4; r++) {
                    float4 v = row[xs * 4 + r];
                    int c0 = xs * 16 + r * 4;
                    __nv_bfloat162 h0 = __floats2bfloat162_rn(v.x, v.y);
                    __nv_bfloat162 h1 = __floats2bfloat162_rn(v.z, v.w);
                    float e0 = v.x - __bfloat162float(__low2bfloat16(h0));
                    float e1 = v.y - __bfloat162float(__high2bfloat16(h0));
                    float e2 = v.z - __bfloat162float(__low2bfloat16(h1));
                    float e3 = v.w - __bfloat162float(__high2bfloat16(h1));
                    __nv_bfloat162 l0 = __floats2bfloat162_rn(e0, e1);
                    __nv_bfloat162 l1 = __floats2bfloat162_rn(e2, e3);
                    *(__nv_bfloat162*)(xh_hi + xd * XH_PITCH + c0)     = h0;
                    *(__nv_bfloat162*)(xh_hi + xd * XH_PITCH + c0 + 2) = h1;
                    *(__nv_bfloat162*)(xh_lo + xd * XH_PITCH + c0)     = l0;
                    *(__nv_bfloat162*)(xh_lo + xd * XH_PITCH + c0 + 2) = l1;
                }
            }

            float acc[2][8][4];
            #pragma unroll
            for (int mt = 0; mt < 2; mt++)
                #pragma unroll
                for (int nt = 0; nt < 8; nt++)
                    #pragma unroll
                    for (int e = 0; e < 4; e++) acc[mt][nt][e] = 0.f;

            // K-loop: 3-stage pipeline, ONE barrier per chunk.
            for (int n = 0; n < NCHK; n++) {
                if (n + 1 < NCHK) {
                    const char* src = Wg + (size_t)(n + 1) * WCHUNK_B + tid * 16;
                    char* dst = wst + ((n + 1) % NSTAGE) * WCHUNK_B + tid * 16;
                    #pragma unroll
                    for (int q = 0; q < 12; q++) cp_async16(dst + q * 4096, src + q * 4096);
                    cp_commit();
                    cp_wait1();
                } else {
                    cp_wait0();
                }
                __syncthreads();   // chunk n visible; prior-chunk reads fenced

                const uint32_t co = (uint32_t)n * 32u;
                uint32_t ah[2][4], al[2][4];
                ldsm_x4(ah[0], xhh_s + aoff + co);
                ldsm_x4(ah[1], xhh_s + 16u * 528u + aoff + co);
                ldsm_x4(al[0], xhl_s + aoff + co);
                ldsm_x4(al[1], xhl_s + 16u * 528u + aoff + co);

                const uint32_t wc = wst_s + (uint32_t)(n % NSTAGE) * WCHUNK_B;
                #pragma unroll
                for (int p = 0; p < 4; p++) {
                    uint32_t bh[4], bl[4];
                    ldsm_x4(bh, wc + brow + (uint32_t)p * 16u * WROW_B);
                    ldsm_x4(bl, wc + WHALF_B + brow + (uint32_t)p * 16u * WROW_B);
                    #pragma unroll
                    for (int mt = 0; mt < 2; mt++) {
                        mma_bf16(acc[mt][2 * p],     ah[mt], bh[0], bh[1]);
                        mma_bf16(acc[mt][2 * p],     al[mt], bh[0], bh[1]);
                        mma_bf16(acc[mt][2 * p],     ah[mt], bl[0], bl[1]);
                        mma_bf16(acc[mt][2 * p + 1], ah[mt], bh[2], bh[3]);
                        mma_bf16(acc[mt][2 * p + 1], al[mt], bh[2], bh[3]);
                        mma_bf16(acc[mt][2 * p + 1], ah[mt], bl[2], bl[3]);
                    }
                }
            }
            __syncthreads();   // all W-stage reads done -> gates may alias

            // C fragments -> gates smem [doc][n] (aliased onto W stages)
            #pragma unroll
            for (int mt = 0; mt < 2; mt++)
                #pragma unroll
                for (int nt = 0; nt < 8; nt++) {
                    int col = wid * 64 + nt * 8 + 2 * t4;
                    *(float2*)(gates + (mt * 16 + g4) * G_PITCH + col) =
                        make_float2(acc[mt][nt][0], acc[mt][nt][1]);
                    *(float2*)(gates + (mt * 16 + g4 + 8) * G_PITCH + col) =
                        make_float2(acc[mt][nt][2], acc[mt][nt][3]);
                }
            __syncthreads();

            // state update: thread owns (doc ud, hps uh0..uh0+7)
            if (st < Lme) {
                #pragma unroll
                for (int i = 0; i < 8; i++) {
                    int hp = uh0 + i;
                    float4 ga = *(float4*)(gates + ud * G_PITCH + hp * 8);
                    float4 gb = *(float4*)(gates + ud * G_PITCH + hp * 8 + 4);
                    float hn0, hn1;
                    {
                        int s = i * 2;
                        float ig = sigf(ga.x), fg = sigf(ga.z), gg = tanh_f(gb.x), og = sigf(gb.z);
                        float c2 = fmaf(fg, creg[s], ig * gg);
                        hn0 = og * tanh_f(c2);
                        creg[s] = c2; sreg[s] += hn0;
                    }
                    {
                        int s = i * 2 + 1;
                        float ig = sigf(ga.y), fg = sigf(ga.w), gg = tanh_f(gb.y), og = sigf(gb.w);
                        float c2 = fmaf(fg, creg[s], ig * gg);
                        hn1 = og * tanh_f(c2);
                        creg[s] = c2; sreg[s] += hn1;
                    }
                    __nv_bfloat162 hh = __floats2bfloat162_rn(hn0, hn1);
                    float e0 = hn0 - __bfloat162float(__low2bfloat16(hh));
                    float e1 = hn1 - __bfloat162float(__high2bfloat16(hh));
                    __nv_bfloat162 hl = __floats2bfloat162_rn(e0, e1);
                    *(__nv_bfloat162*)(xh_hi + ud * XH_PITCH + 128 + hp * 2) = hh;
                    *(__nv_bfloat162*)(xh_lo + ud * XH_PITCH + 128 + hp * 2) = hl;
                }
            }
            __syncthreads();   // gates region free for next step's chunk-0 cp
        }

        // epilogue: mean-pooled embedding
        {
            float inv = 1.f / (float)Lme;
            #pragma unroll
            for (int i = 0; i < 8; i++) {
                int hp = uh0 + i;
                g_demb[(size_t)Did[ud] * 256 + dir * 128 + hp * 2]     = sreg[i * 2] * inv;
                g_demb[(size_t)Did[ud] * 256 + dir * 128 + hp * 2 + 1] = sreg[i * 2 + 1] * inv;
            }
        }
    }
}

// ---------------------------------------------------------------------------
// Layer 2: unchanged SIMT f32x2 path (proven; ~50us)
// ---------------------------------------------------------------------------
__device__ __forceinline__ void ffma2(unsigned long long& d,
                                      unsigned long long a, unsigned long long b) {
    asm("fma.rn.f32x2 %0, %1, %2, %0;" : "+l"(d) : "l"(a), "l"(b));
}
__device__ __forceinline__ unsigned long long dup2(float x) {
    unsigned long long r;
    asm("mov.b64 %0, {%1, %1};" : "=l"(r) : "f"(x));
    return r;
}
__device__ __forceinline__ float2 unpack2(unsigned long long v) {
    float2 r;
    asm("mov.b64 {%0, %1}, %2;" : "=f"(r.x), "=f"(r.y) : "l"(v));
    return r;
}

__global__ void __launch_bounds__(256, 1)
lstm2_kernel(const int* __restrict__ nidx, const int* __restrict__ nlens,
             const int* __restrict__ gnum, float* __restrict__ out) {
    extern __shared__ float sm[];
    float* xh = sm;
    float* cs = sm + 2560;
    float* ss = sm + 3072;
    float* wb = sm + 3584;
    int*   Ls = (int*)(sm + 3584 + 2 * KC2 * GATES2);

    const int tid  = threadIdx.x;
    const int dir  = blockIdx.y;
    const int tile = blockIdx.x;
    const float* Wt = g_Wt2 + (size_t)dir * KTOT2 * GATES2;

    if (tid < TILE2) Ls[tid] = nlens[tile * TILE2 + tid];
    for (int i = tid; i < 1536; i += 256) sm[2048 + i] = 0.f;
    __syncthreads();

    int maxlen = 0;
    #pragma unroll
    for (int i = 0; i < TILE2; i++) maxlen = max(maxlen, Ls[i]);

    const int ng = tid & 3;
    const int hh = tid >> 2;
    const int xn = tid >> 5;
    const int xq = tid & 31;

    for (int st = 0; st < maxlen; ++st) {
        {
            const float4* src = (const float4*)Wt + tid;
            float4* dst = (float4*)wb + tid;
            #pragma unroll
            for (int q = 0; q < 16; q++) cp_async16(dst + 256 * q, src + 256 * q);
            cp_commit();
        }
        {
            int L  = Ls[xn];
            int te = (dir == 0) ? st : (L - 1 - st);
            te = min(max(te, 0), KSTEPS - 1);
            int gn = tile * TILE2 + xn;
            int didx = nidx[gn * KSTEPS + te];
            const float4* row = (const float4*)(g_demb + (size_t)didx * 256);
            #pragma unroll
            for (int r = 0; r < 2; r++) {
                float4 v = row[xq * 2 + r];
                int k0 = xq * 8 + r * 4;
                xh[(k0 + 0) * TILE2 + xn] = v.x;
                xh[(k0 + 1) * TILE2 + xn] = v.y;
                xh[(k0 + 2) * TILE2 + xn] = v.z;
                xh[(k0 + 3) * TILE2 + xn] = v.w;
            }
        }
        __syncthreads();

        unsigned long long acc[4];
        #pragma unroll
        for (int b = 0; b < 4; b++) acc[b] = 0ull;

        for (int n = 0; n < NCH2; n++) {
            if (n + 1 < NCH2) {
                const float4* src = (const float4*)(Wt + (size_t)(n + 1) * KC2 * GATES2) + tid;
                float4* dst = (float4*)(wb + ((n + 1) & 1) * (KC2 * GATES2)) + tid;
                #pragma unroll
                for (int q = 0; q < 16; q++) cp_async16(dst + 256 * q, src + 256 * q);
                cp_commit();
                cp_wait1();
            } else {
                cp_wait0();
            }
            __syncthreads();

            const float* W  = wb + (n & 1) * (KC2 * GATES2);
            const float* xk = xh + n * KC2 * TILE2;
            #pragma unroll 4
            for (int kc = 0; kc < KC2; kc++) {
                unsigned long long xv = *(const unsigned long long*)(xk + kc * TILE2 + (ng << 1));
                #pragma unroll
                for (int b = 0; b < 4; b++) {
                    unsigned long long wp = dup2(W[kc * GATES2 + b * HID2 + hh]);
                    ffma2(acc[b], wp, xv);
                }
            }
            __syncthreads();
        }

        {
            float2 gi2 = unpack2(acc[0]);
            float2 gf2 = unpack2(acc[1]);
            float2 gg2 = unpack2(acc[2]);
            float2 go2 = unpack2(acc[3]);
            float gia[2] = { gi2.x, gi2.y };
            float gfa[2] = { gf2.x, gf2.y };
            float gga[2] = { gg2.x, gg2.y };
            float goa[2] = { go2.x, go2.y };
            #pragma unroll
            for (int e = 0; e < 2; e++) {
                int nd = (ng << 1) + e;
                float co = cs[hh * TILE2 + nd];
                float ho = xh[(256 + hh) * TILE2 + nd];
                float so = ss[hh * TILE2 + nd];
                float ig = sigf(gia[e]);
                float fg = sigf(gfa[e]);
                float gg = tanh_f(gga[e]);
                float og = sigf(goa[e]);
                float c2v = fmaf(fg, co, ig * gg);
                float h2v = og * tanh_f(c2v);
                bool act = st < Ls[nd];
                cs[hh * TILE2 + nd] = act ? c2v : co;
                xh[(256 + hh) * TILE2 + nd] = act ? h2v : ho;
                ss[hh * TILE2 + nd] = act ? (so + h2v) : so;
            }
        }
        __syncthreads();
    }

    {
        #pragma unroll
        for (int e = 0; e < 2; e++) {
            int nd = (ng << 1) + e;
            int gn = tile * TILE2 + nd;
            int gi = gn >> 6;
            int ni = gn & 63;
            float gm = (ni < gnum[gi]) ? 1.f : 0.f;
            float v = ss[hh * TILE2 + nd] / (float)Ls[nd] * gm;
            out[(size_t)gn * 128 + dir * 64 + hh] = v;
            if (dir == 0 && hh == 0) out[NNODES * 128 + gn] = gm;
        }
    }
}

// ---------------------------------------------------------------------------
// Launch
// ---------------------------------------------------------------------------
extern "C" void kernel_launch(void* const* d_in, const int* in_sizes, int n_in,
                              void* d_out, int out_size) {
    const float* docs  = (const float*)d_in[0];
    const int*   dlens = (const int*)  d_in[1];
    const int*   nidx  = (const int*)  d_in[2];
    const int*   nlens = (const int*)  d_in[3];
    const int*   gnum  = (const int*)  d_in[4];
    const float* Wih1f = (const float*)d_in[5];
    const float* Whh1f = (const float*)d_in[6];
    const float* Wih1b = (const float*)d_in[7];
    const float* Whh1b = (const float*)d_in[8];
    const float* Wih2f = (const float*)d_in[9];
    const float* Whh2f = (const float*)d_in[10];
    const float* Wih2b = (const float*)d_in[11];
    const float* Whh2b = (const float*)d_in[12];
    float* out = (float*)d_out;

    const size_t sm1 = SM1_TOTAL;                                               // 181504 B
    const size_t sm2 = (size_t)(3584 + 2 * KC2 * GATES2) * 4 + TILE2 * 4 + 32;  // ~145 KB
    cudaFuncSetAttribute(lstm1_kernel, cudaFuncAttributeMaxDynamicSharedMemorySize, (int)sm1);
    cudaFuncSetAttribute(lstm2_kernel, cudaFuncAttributeMaxDynamicSharedMemorySize, (int)sm2);

    prep_w1_kernel<<<dim3(NCHK, 2), 512>>>(Wih1f, Whh1f, Wih1b, Whh1b);
    transpose2_kernel<<<dim3(256, 2), 320>>>(Wih2f, Whh2f, Wih2b, Whh2b);
    sort_kernel<<<1, 1024>>>(dlens);
    lstm1_kernel<<<dim3(NPAIR, 2), NT1, sm1>>>(docs, dlens);
    lstm2_kernel<<<dim3(NNODES / TILE2, 2), 256, sm2>>>(nidx, nlens, gnum, out);
    (void)in_sizes; (void)n_in; (void)out_size;
}

// round 17
// speedup vs baseline: 2.0581x; 1.1785x over previous
#include <cuda_runtime.h>
#include <cuda_bf16.h>
#include <cstdint>

// ---------------------------------------------------------------------------
// Problem constants
// ---------------------------------------------------------------------------
#define TDOCS 4096
#define TSEQ  64
#define DIM   128
#define HID   128
#define GATES 512
#define TILE1 32       // docs per CTA tile (layer 1)
#define NC16  16       // 16-wide k chunks in W layout
#define NC32  8        // 32-wide k chunks in the pipeline
#define NT1   256      // threads layer 1 (8 warps)
#define NPAIR 64       // tile pairs: CTA p runs tiles p and 127-p

#define NNODES 512
#define KSTEPS 8
#define HID2   64
#define GATES2 256
#define KTOT2  320
#define TILE2  8
#define KC2    64
#define NCH2   5

// Layer-1 W dense-tile layout:
//   [dir][c16][half(hi/lo)][tile(nt,s)][8 rows x 16B]
//   n = hp*8 + b*2 + r  <->  gate row g = b*128 + 2*hp + r   (b: i,f,g,o)
//   nt = n>>3, row-in-tile = n&7; k: s = kk>>3, elem = kk&7.
//   chunk16 = 2*8192 elems = 32768 B (hi 16384 | lo 16384), no padding.
#define K16HALF_B 16384
#define K16_B     32768
#define STG_B     65536                    // K=32 stage = 2 chunk16
#define NSTG      2

// smem layout (bytes), layer 1
#define XH_PITCH 264                       // bf16 per row (528 B)
#define SM_XHHI  0
#define SM_XHLO  16896                     // 32*264*2
#define SM_WST   33792                     // 2 stages x 65536 = 131072
#define G_PITCH  520                       // gates aliased onto W stages
#define SM_LS    164864                    // Ls[32], Did[32]
#define SM1_TOTAL 165120

// ---------------------------------------------------------------------------
// Device scratch
// ---------------------------------------------------------------------------
__device__ __nv_bfloat16 g_W1s[2 * NC16 * 2 * 8192];   // 1 MB dense
__device__ float g_Wt2[2 * KTOT2 * GATES2];
__device__ float g_demb[TDOCS * 256];
__device__ int   g_perm[TDOCS];

// ---------------------------------------------------------------------------
// Helpers
// ---------------------------------------------------------------------------
__device__ __forceinline__ float sigf(float x) {
    return __fdividef(1.f, 1.f + __expf(-x));
}
__device__ __forceinline__ float tanh_f(float x) {
    return fmaf(2.f, __fdividef(1.f, 1.f + __expf(-2.f * x)), -1.f);
}
__device__ __forceinline__ unsigned smem_u32(const void* p) {
    return (unsigned)__cvta_generic_to_shared(p);
}
__device__ __forceinline__ void cp_async16(void* dst_smem, const void* src_gmem) {
    unsigned s = smem_u32(dst_smem);
    asm volatile("cp.async.ca.shared.global [%0], [%1], 16;\n" :: "r"(s), "l"(src_gmem));
}
__device__ __forceinline__ void cp_commit() { asm volatile("cp.async.commit_group;\n"); }
__device__ __forceinline__ void cp_wait0()  { asm volatile("cp.async.wait_group 0;\n"); }

__device__ __forceinline__ void ldsm_x4(uint32_t* r, uint32_t addr) {
    asm volatile("ldmatrix.sync.aligned.m8n8.x4.shared.b16 {%0,%1,%2,%3}, [%4];"
                 : "=r"(r[0]), "=r"(r[1]), "=r"(r[2]), "=r"(r[3]) : "r"(addr));
}
__device__ __forceinline__ void mma_bf16(float* c, const uint32_t* a, uint32_t b0, uint32_t b1) {
    asm volatile("mma.sync.aligned.m16n8k16.row.col.f32.bf16.bf16.f32 "
                 "{%0,%1,%2,%3}, {%4,%5,%6,%7}, {%8,%9}, {%0,%1,%2,%3};"
                 : "+f"(c[0]), "+f"(c[1]), "+f"(c[2]), "+f"(c[3])
                 : "r"(a[0]), "r"(a[1]), "r"(a[2]), "r"(a[3]), "r"(b0), "r"(b1));
}

// ---------------------------------------------------------------------------
// Prep: layer-1 W -> bf16 hi/lo, dense 8x8 ldmatrix tiles, gate-interleaved n
// ---------------------------------------------------------------------------
__global__ void prep_w1_kernel(const float* __restrict__ Wihf, const float* __restrict__ Whhf,
                               const float* __restrict__ Wihb, const float* __restrict__ Whhb) {
    int n = threadIdx.x;         // 0..511 interleaved gate index
    int c = blockIdx.x;          // chunk16 0..15
    int dir = blockIdx.y;
    const float* Wih = dir ? Wihb : Wihf;
    const float* Whh = dir ? Whhb : Whhf;
    int hp = n >> 3, b = (n >> 1) & 3, r = n & 1;
    int g = b * 128 + hp * 2 + r;
    int nt = n >> 3, rr = n & 7;
    size_t basehi = (size_t)((dir * NC16 + c) * 2 + 0) * 8192;
    size_t baselo = (size_t)((dir * NC16 + c) * 2 + 1) * 8192;
    for (int kk = 0; kk < 16; kk++) {
        int k = c * 16 + kk;
        int s = kk >> 3, e = kk & 7;
        int off = (nt * 2 + s) * 64 + rr * 8 + e;
        float w = (k < 128) ? Wih[g * 128 + k] : Whh[g * 128 + (k - 128)];
        __nv_bfloat16 hi = __float2bfloat16_rn(w);
        float res = w - __bfloat162float(hi);
        g_W1s[basehi + off] = hi;
        g_W1s[baselo + off] = __float2bfloat16_rn(res);
    }
}

__global__ void transpose2_kernel(const float* __restrict__ Wihf, const float* __restrict__ Whhf,
                                  const float* __restrict__ Wihb, const float* __restrict__ Whhb) {
    int g = blockIdx.x, k = threadIdx.x, dir = blockIdx.y;
    const float* Wih = dir ? Wihb : Wihf;
    const float* Whh = dir ? Whhb : Whhf;
    float v = (k < 256) ? Wih[g * 256 + k] : Whh[g * 64 + (k - 256)];
    g_Wt2[((size_t)dir * KTOT2 + k) * GATES2 + g] = v;
}

__global__ void sort_kernel(const int* __restrict__ lens) {
    __shared__ int hist[TSEQ + 1];
    __shared__ int cur[TSEQ + 1];
    int tid = threadIdx.x;
    if (tid <= TSEQ) hist[tid] = 0;
    __syncthreads();
    for (int i = tid; i < TDOCS; i += blockDim.x) atomicAdd(&hist[lens[i]], 1);
    __syncthreads();
    if (tid == 0) {
        int acc = 0;
        for (int l = TSEQ; l >= 1; l--) { cur[l] = acc; acc += hist[l]; }
    }
    __syncthreads();
    for (int i = tid; i < TDOCS; i += blockDim.x) {
        int l = lens[i];
        int p = atomicAdd(&cur[l], 1);
        g_perm[p] = i;
    }
}

// ---------------------------------------------------------------------------
// Layer 1: BiLSTM via mma.sync bf16 3-term split. CTA = tile pair (p,127-p).
// K=32 chunks (8/step), dense W tiles, 2-stage cp.async double buffer with
// cp issued AFTER each chunk barrier (write-target last read 2 chunks ago,
// fenced). One barrier per chunk; 11 barriers/step total.
// ---------------------------------------------------------------------------
__global__ void __launch_bounds__(NT1, 1)
lstm1_kernel(const float* __restrict__ docs, const int* __restrict__ lens) {
    extern __shared__ char smc[];
    __nv_bfloat16* xh_hi = (__nv_bfloat16*)(smc + SM_XHHI);
    __nv_bfloat16* xh_lo = (__nv_bfloat16*)(smc + SM_XHLO);
    char*  wst   = smc + SM_WST;                 // 2 stages of 65536 B
    float* gates = (float*)(smc + SM_WST);       // ALIAS: valid only post-loop
    int*   Ls    = (int*)(smc + SM_LS);
    int*   Did   = Ls + TILE1;

    const int tid  = threadIdx.x;
    const int dir  = blockIdx.y;
    const int pairid = blockIdx.x;
    const char* Wg = (const char*)g_W1s + (size_t)dir * NC16 * K16_B;

    const int wid  = tid >> 5;
    const int lane = tid & 31;
    const int g4   = lane >> 2;
    const int t4   = lane & 3;

    const uint32_t xhh_s = smem_u32(xh_hi);
    const uint32_t xhl_s = smem_u32(xh_lo);
    const uint32_t wst_s = smem_u32(wst);
    const uint32_t aoff  = (uint32_t)(lane & 15) * 528u + (uint32_t)(lane >> 4) * 16u;
    // dense-tile B: x4 covers 2 n-tiles x k16; addr = tilebase + lane*16
    const uint32_t bbase = (uint32_t)(wid * 2048) + (uint32_t)lane * 16u;

    const int ud  = tid >> 3;          // update doc 0..31
    const int uh0 = (tid & 7) * 8;     // update hp base
    const int xd  = tid >> 3;          // x-load doc
    const int xs  = tid & 7;           // x-load slice (16 floats)

    for (int half = 0; half < 2; half++) {
        const int tile = half ? (2 * NPAIR - 1 - pairid) : pairid;

        __syncthreads();   // previous half fully done before smem reinit
        if (tid < TILE1) {
            int d = g_perm[tile * TILE1 + tid];
            Did[tid] = d;
            Ls[tid]  = lens[d];
        }
        // zero XH hi+lo
        {
            uint32_t* z = (uint32_t*)smc;
            for (int i = tid; i < 8448; i += NT1) z[i] = 0u;
        }
        __syncthreads();

        int maxlen = 0;
        #pragma unroll 8
        for (int i = 0; i < TILE1; i++) maxlen = max(maxlen, Ls[i]);

        const int Lme = Ls[ud];
        float creg[16], sreg[16];
        #pragma unroll
        for (int s = 0; s < 16; s++) { creg[s] = 0.f; sreg[s] = 0.f; }

        for (int st = 0; st < maxlen; ++st) {
            // issue stage 0 <- K32 chunk 0 (safe: post end-of-step barrier)
            {
                const char* src = Wg + tid * 16;
                char* dst = wst + tid * 16;
                #pragma unroll
                for (int q = 0; q < 16; q++) cp_async16(dst + q * 4096, src + q * 4096);
                cp_commit();
            }
            // x_t load, split to bf16 hi/lo, store row-major into XH
            {
                int L  = Ls[xd];
                int tt = (dir == 0) ? st : (L - 1 - st);
                tt = min(max(tt, 0), TSEQ - 1);
                const float4* row = (const float4*)(docs + ((size_t)Did[xd] * TSEQ + tt) * DIM);
                #pragma unroll
                for (int r = 0; r < 4; r++) {
                    float4 v = row[xs * 4 + r];
                    int c0 = xs * 16 + r * 4;
                    __nv_bfloat162 h0 = __floats2bfloat162_rn(v.x, v.y);
                    __nv_bfloat162 h1 = __floats2bfloat162_rn(v.z, v.w);
                    float e0 = v.x - __bfloat162float(__low2bfloat16(h0));
                    float e1 = v.y - __bfloat162float(__high2bfloat16(h0));
                    float e2 = v.z - __bfloat162float(__low2bfloat16(h1));
                    float e3 = v.w - __bfloat162float(__high2bfloat16(h1));
                    __nv_bfloat162 l0 = __floats2bfloat162_rn(e0, e1);
                    __nv_bfloat162 l1 = __floats2bfloat162_rn(e2, e3);
                    *(__nv_bfloat162*)(xh_hi + xd * XH_PITCH + c0)     = h0;
                    *(__nv_bfloat162*)(xh_hi + xd * XH_PITCH + c0 + 2) = h1;
                    *(__nv_bfloat162*)(xh_lo + xd * XH_PITCH + c0)     = l0;
                    *(__nv_bfloat162*)(xh_lo + xd * XH_PITCH + c0 + 2) = l1;
                }
            }

            float acc[2][8][4];
            #pragma unroll
            for (int mt = 0; mt < 2; mt++)
                #pragma unroll
                for (int nt = 0; nt < 8; nt++)
                    #pragma unroll
                    for (int e = 0; e < 4; e++) acc[mt][nt][e] = 0.f;

            // K-loop: 8 K32 chunks, 2-stage buffer, cp AFTER barrier.
            for (int c = 0; c < NC32; c++) {
                cp_wait0();        // stage c&1 ready
                __syncthreads();   // visible to all; chunk c-1 reads fenced
                if (c + 1 < NC32) {
                    const char* src = Wg + (size_t)(c + 1) * STG_B + tid * 16;
                    char* dst = wst + ((c + 1) & 1) * STG_B + tid * 16;
                    #pragma unroll
                    for (int q = 0; q < 16; q++) cp_async16(dst + q * 4096, src + q * 4096);
                    cp_commit();
                }

                const uint32_t stg = wst_s + (uint32_t)(c & 1) * STG_B;
                #pragma unroll
                for (int ksc = 0; ksc < 2; ksc++) {
                    const uint32_t co = (uint32_t)(c * 2 + ksc) * 32u;
                    uint32_t ah[2][4], al[2][4];
                    ldsm_x4(ah[0], xhh_s + aoff + co);
                    ldsm_x4(ah[1], xhh_s + 16u * 528u + aoff + co);
                    ldsm_x4(al[0], xhl_s + aoff + co);
                    ldsm_x4(al[1], xhl_s + 16u * 528u + aoff + co);

                    const uint32_t wb = stg + (uint32_t)ksc * K16_B + bbase;
                    #pragma unroll
                    for (int p = 0; p < 4; p++) {
                        uint32_t bh[4], bl[4];
                        ldsm_x4(bh, wb + (uint32_t)p * 512u);
                        ldsm_x4(bl, wb + K16HALF_B + (uint32_t)p * 512u);
                        #pragma unroll
                        for (int mt = 0; mt < 2; mt++) {
                            mma_bf16(acc[mt][2 * p],     ah[mt], bh[0], bh[1]);
                            mma_bf16(acc[mt][2 * p],     al[mt], bh[0], bh[1]);
                            mma_bf16(acc[mt][2 * p],     ah[mt], bl[0], bl[1]);
                            mma_bf16(acc[mt][2 * p + 1], ah[mt], bh[2], bh[3]);
                            mma_bf16(acc[mt][2 * p + 1], al[mt], bh[2], bh[3]);
                            mma_bf16(acc[mt][2 * p + 1], ah[mt], bl[2], bl[3]);
                        }
                    }
                }
            }
            __syncthreads();   // all W-stage reads done -> gates may alias

            // C fragments -> gates smem [doc][n]
            #pragma unroll
            for (int mt = 0; mt < 2; mt++)
                #pragma unroll
                for (int nt = 0; nt < 8; nt++) {
                    int col = wid * 64 + nt * 8 + 2 * t4;
                    *(float2*)(gates + (mt * 16 + g4) * G_PITCH + col) =
                        make_float2(acc[mt][nt][0], acc[mt][nt][1]);
                    *(float2*)(gates + (mt * 16 + g4 + 8) * G_PITCH + col) =
                        make_float2(acc[mt][nt][2], acc[mt][nt][3]);
                }
            __syncthreads();

            // state update: thread owns (doc ud, hps uh0..uh0+7)
            if (st < Lme) {
                #pragma unroll
                for (int i = 0; i < 8; i++) {
                    int hp = uh0 + i;
                    float4 ga = *(float4*)(gates + ud * G_PITCH + hp * 8);
                    float4 gb = *(float4*)(gates + ud * G_PITCH + hp * 8 + 4);
                    float hn0, hn1;
                    {
                        int s = i * 2;
                        float ig = sigf(ga.x), fg = sigf(ga.z), gg = tanh_f(gb.x), og = sigf(gb.z);
                        float c2 = fmaf(fg, creg[s], ig * gg);
                        hn0 = og * tanh_f(c2);
                        creg[s] = c2; sreg[s] += hn0;
                    }
                    {
                        int s = i * 2 + 1;
                        float ig = sigf(ga.y), fg = sigf(ga.w), gg = tanh_f(gb.y), og = sigf(gb.w);
                        float c2 = fmaf(fg, creg[s], ig * gg);
                        hn1 = og * tanh_f(c2);
                        creg[s] = c2; sreg[s] += hn1;
                    }
                    __nv_bfloat162 hh = __floats2bfloat162_rn(hn0, hn1);
                    float e0 = hn0 - __bfloat162float(__low2bfloat16(hh));
                    float e1 = hn1 - __bfloat162float(__high2bfloat16(hh));
                    __nv_bfloat162 hl = __floats2bfloat162_rn(e0, e1);
                    *(__nv_bfloat162*)(xh_hi + ud * XH_PITCH + 128 + hp * 2) = hh;
                    *(__nv_bfloat162*)(xh_lo + ud * XH_PITCH + 128 + hp * 2) = hl;
                }
            }
            __syncthreads();   // gates region free for next step's stage-0 cp
        }

        // epilogue: mean-pooled embedding
        {
            float inv = 1.f / (float)Lme;
            #pragma unroll
            for (int i = 0; i < 8; i++) {
                int hp = uh0 + i;
                g_demb[(size_t)Did[ud] * 256 + dir * 128 + hp * 2]     = sreg[i * 2] * inv;
                g_demb[(size_t)Did[ud] * 256 + dir * 128 + hp * 2 + 1] = sreg[i * 2 + 1] * inv;
            }
        }
    }
}

// ---------------------------------------------------------------------------
// Layer 2: unchanged SIMT f32x2 path (proven; ~50us)
// ---------------------------------------------------------------------------
__device__ __forceinline__ void cp_wait1()  { asm volatile("cp.async.wait_group 1;\n"); }
__device__ __forceinline__ void ffma2(unsigned long long& d,
                                      unsigned long long a, unsigned long long b) {
    asm("fma.rn.f32x2 %0, %1, %2, %0;" : "+l"(d) : "l"(a), "l"(b));
}
__device__ __forceinline__ unsigned long long dup2(float x) {
    unsigned long long r;
    asm("mov.b64 %0, {%1, %1};" : "=l"(r) : "f"(x));
    return r;
}
__device__ __forceinline__ float2 unpack2(unsigned long long v) {
    float2 r;
    asm("mov.b64 {%0, %1}, %2;" : "=f"(r.x), "=f"(r.y) : "l"(v));
    return r;
}

__global__ void __launch_bounds__(256, 1)
lstm2_kernel(const int* __restrict__ nidx, const int* __restrict__ nlens,
             const int* __restrict__ gnum, float* __restrict__ out) {
    extern __shared__ float sm[];
    float* xh = sm;
    float* cs = sm + 2560;
    float* ss = sm + 3072;
    float* wb = sm + 3584;
    int*   Ls = (int*)(sm + 3584 + 2 * KC2 * GATES2);

    const int tid  = threadIdx.x;
    const int dir  = blockIdx.y;
    const int tile = blockIdx.x;
    const float* Wt = g_Wt2 + (size_t)dir * KTOT2 * GATES2;

    if (tid < TILE2) Ls[tid] = nlens[tile * TILE2 + tid];
    for (int i = tid; i < 1536; i += 256) sm[2048 + i] = 0.f;
    __syncthreads();

    int maxlen = 0;
    #pragma unroll
    for (int i = 0; i < TILE2; i++) maxlen = max(maxlen, Ls[i]);

    const int ng = tid & 3;
    const int hh = tid >> 2;
    const int xn = tid >> 5;
    const int xq = tid & 31;

    for (int st = 0; st < maxlen; ++st) {
        {
            const float4* src = (const float4*)Wt + tid;
            float4* dst = (float4*)wb + tid;
            #pragma unroll
            for (int q = 0; q < 16; q++) cp_async16(dst + 256 * q, src + 256 * q);
            cp_commit();
        }
        {
            int L  = Ls[xn];
            int te = (dir == 0) ? st : (L - 1 - st);
            te = min(max(te, 0), KSTEPS - 1);
            int gn = tile * TILE2 + xn;
            int didx = nidx[gn * KSTEPS + te];
            const float4* row = (const float4*)(g_demb + (size_t)didx * 256);
            #pragma unroll
            for (int r = 0; r < 2; r++) {
                float4 v = row[xq * 2 + r];
                int k0 = xq * 8 + r * 4;
                xh[(k0 + 0) * TILE2 + xn] = v.x;
                xh[(k0 + 1) * TILE2 + xn] = v.y;
                xh[(k0 + 2) * TILE2 + xn] = v.z;
                xh[(k0 + 3) * TILE2 + xn] = v.w;
            }
        }
        __syncthreads();

        unsigned long long acc[4];
        #pragma unroll
        for (int b = 0; b < 4; b++) acc[b] = 0ull;

        for (int n = 0; n < NCH2; n++) {
            if (n + 1 < NCH2) {
                const float4* src = (const float4*)(Wt + (size_t)(n + 1) * KC2 * GATES2) + tid;
                float4* dst = (float4*)(wb + ((n + 1) & 1) * (KC2 * GATES2)) + tid;
                #pragma unroll
                for (int q = 0; q < 16; q++) cp_async16(dst + 256 * q, src + 256 * q);
                cp_commit();
                cp_wait1();
            } else {
                cp_wait0();
            }
            __syncthreads();

            const float* W  = wb + (n & 1) * (KC2 * GATES2);
            const float* xk = xh + n * KC2 * TILE2;
            #pragma unroll 4
            for (int kc = 0; kc < KC2; kc++) {
                unsigned long long xv = *(const unsigned long long*)(xk + kc * TILE2 + (ng << 1));
                #pragma unroll
                for (int b = 0; b < 4; b++) {
                    unsigned long long wp = dup2(W[kc * GATES2 + b * HID2 + hh]);
                    ffma2(acc[b], wp, xv);
                }
            }
            __syncthreads();
        }

        {
            float2 gi2 = unpack2(acc[0]);
            float2 gf2 = unpack2(acc[1]);
            float2 gg2 = unpack2(acc[2]);
            float2 go2 = unpack2(acc[3]);
            float gia[2] = { gi2.x, gi2.y };
            float gfa[2] = { gf2.x, gf2.y };
            float gga[2] = { gg2.x, gg2.y };
            float goa[2] = { go2.x, go2.y };
            #pragma unroll
            for (int e = 0; e < 2; e++) {
                int nd = (ng << 1) + e;
                float co = cs[hh * TILE2 + nd];
                float ho = xh[(256 + hh) * TILE2 + nd];
                float so = ss[hh * TILE2 + nd];
                float ig = sigf(gia[e]);
                float fg = sigf(gfa[e]);
                float gg = tanh_f(gga[e]);
                float og = sigf(goa[e]);
                float c2v = fmaf(fg, co, ig * gg);
                float h2v = og * tanh_f(c2v);
                bool act = st < Ls[nd];
                cs[hh * TILE2 + nd] = act ? c2v : co;
                xh[(256 + hh) * TILE2 + nd] = act ? h2v : ho;
                ss[hh * TILE2 + nd] = act ? (so + h2v) : so;
            }
        }
        __syncthreads();
    }

    {
        #pragma unroll
        for (int e = 0; e < 2; e++) {
            int nd = (ng << 1) + e;
            int gn = tile * TILE2 + nd;
            int gi = gn >> 6;
            int ni = gn & 63;
            float gm = (ni < gnum[gi]) ? 1.f : 0.f;
            float v = ss[hh * TILE2 + nd] / (float)Ls[nd] * gm;
            out[(size_t)gn * 128 + dir * 64 + hh] = v;
            if (dir == 0 && hh == 0) out[NNODES * 128 + gn] = gm;
        }
    }
}

// ---------------------------------------------------------------------------
// Launch
// ---------------------------------------------------------------------------
extern "C" void kernel_launch(void* const* d_in, const int* in_sizes, int n_in,
                              void* d_out, int out_size) {
    const float* docs  = (const float*)d_in[0];
    const int*   dlens = (const int*)  d_in[1];
    const int*   nidx  = (const int*)  d_in[2];
    const int*   nlens = (const int*)  d_in[3];
    const int*   gnum  = (const int*)  d_in[4];
    const float* Wih1f = (const float*)d_in[5];
    const float* Whh1f = (const float*)d_in[6];
    const float* Wih1b = (const float*)d_in[7];
    const float* Whh1b = (const float*)d_in[8];
    const float* Wih2f = (const float*)d_in[9];
    const float* Whh2f = (const float*)d_in[10];
    const float* Wih2b = (const float*)d_in[11];
    const float* Whh2b = (const float*)d_in[12];
    float* out = (float*)d_out;

    const size_t sm1 = SM1_TOTAL;                                               // 165120 B
    const size_t sm2 = (size_t)(3584 + 2 * KC2 * GATES2) * 4 + TILE2 * 4 + 32;  // ~145 KB
    cudaFuncSetAttribute(lstm1_kernel, cudaFuncAttributeMaxDynamicSharedMemorySize, (int)sm1);
    cudaFuncSetAttribute(lstm2_kernel, cudaFuncAttributeMaxDynamicSharedMemorySize, (int)sm2);

    prep_w1_kernel<<<dim3(NC16, 2), 512>>>(Wih1f, Whh1f, Wih1b, Whh1b);
    transpose2_kernel<<<dim3(256, 2), 320>>>(Wih2f, Whh2f, Wih2b, Whh2b);
    sort_kernel<<<1, 1024>>>(dlens);
    lstm1_kernel<<<dim3(NPAIR, 2), NT1, sm1>>>(docs, dlens);
    lstm2_kernel<<<dim3(NNODES / TILE2, 2), 256, sm2>>>(nidx, nlens, gnum, out);
    (void)in_sizes; (void)n_in; (void)out_size;
}